// round 8
// baseline (speedup 1.0000x reference)
#include <cuda_runtime.h>
#include <cuda_bf16.h>
#include <math.h>

#define NN 100000
#define NE 1600000
#define NG 512
#define NSB 98   // scan blocks of 1024 -> covers 100352 >= NN

// ---------------- device scratch ----------------
__device__ __align__(256) __nv_bfloat162 g_yb[NN * 32];  // y in bf16x2: 128B/node
__device__ __align__(256) float g_t[NN * 64];
__device__ float g_stats[4 * 128];
__device__ float g_scale[64];
__device__ float g_shift[64];
__device__ float g_pooled[NG * 256];
__device__ float g_head1[NG * 64];
__device__ int   g_deg[NN];
__device__ int   g_off[NN + 1];
__device__ int   g_cursor[NN];
__device__ int   g_srcs[NE];
__device__ int   g_bsum[NSB];
__device__ int   g_boff[NSB];

// ---------------- f32x2 helpers ----------------
__device__ __forceinline__ unsigned long long f32x2_dup(float x) {
    unsigned long long r;
    asm("mov.b64 %0, {%1, %1};" : "=l"(r) : "f"(x));
    return r;
}
__device__ __forceinline__ void f32x2_fma(unsigned long long &d,
                                          unsigned long long a, unsigned long long b) {
    asm("fma.rn.f32x2 %0, %1, %2, %0;" : "+l"(d) : "l"(a), "l"(b));
}
__device__ __forceinline__ float2 f32x2_unpack(unsigned long long v) {
    float2 r;
    asm("mov.b64 {%0, %1}, %2;" : "=f"(r.x), "=f"(r.y) : "l"(v));
    return r;
}
// bf16x2 (packed in u32) -> two f32x2-duplicated weights (exact expansion)
__device__ __forceinline__ void wpair_from_bf16x2(unsigned r,
                                                  unsigned long long &wx,
                                                  unsigned long long &wy) {
    wx = f32x2_dup(__uint_as_float(r << 16));
    wy = f32x2_dup(__uint_as_float(r & 0xffff0000u));
}
__device__ __forceinline__ unsigned bf16x2_pack(float a, float b) {
    __nv_bfloat162 v = __floats2bfloat162_rn(a, b);
    return *(unsigned*)&v;
}

// ---------------- fused zero kernel ----------------
#define ZW (131072 + 512 + NN)
__global__ void zero_all_kernel() {
    int i = blockIdx.x * 256 + threadIdx.x;
    if (i < 131072) g_pooled[i] = 0.f;
    else if (i < 131072 + 512) g_stats[i - 131072] = 0.f;
    else if (i < ZW) g_deg[i - 131072 - 512] = 0;
}

// ---------------- CSR build ----------------
__global__ void hist_kernel(const int* __restrict__ ei) {
    int e = blockIdx.x * 256 + threadIdx.x;
    if (e < NE) atomicAdd(&g_deg[ei[NE + e]], 1);
}
__global__ void scan1_kernel() {                  // <<<NSB,1024>>>
    __shared__ int wsum[32];
    int tid = threadIdx.x;
    int i = blockIdx.x * 1024 + tid;
    int v = (i < NN) ? g_deg[i] : 0;
    int x = v;
    #pragma unroll
    for (int o = 1; o < 32; o <<= 1) {
        int t = __shfl_up_sync(0xffffffffu, x, o);
        if ((tid & 31) >= o) x += t;
    }
    if ((tid & 31) == 31) wsum[tid >> 5] = x;
    __syncthreads();
    if (tid < 32) {
        int y = wsum[tid];
        #pragma unroll
        for (int o = 1; o < 32; o <<= 1) {
            int t = __shfl_up_sync(0xffffffffu, y, o);
            if (tid >= o) y += t;
        }
        wsum[tid] = y;
    }
    __syncthreads();
    int base = (tid >= 32) ? wsum[(tid >> 5) - 1] : 0;
    int incl = x + base;
    if (i < NN) g_off[i] = incl - v;
    if (tid == 1023) g_bsum[blockIdx.x] = incl;
}
__global__ void scan2_kernel() {                  // <<<1,128>>>
    __shared__ int s[128];
    int tid = threadIdx.x;
    int v = (tid < NSB) ? g_bsum[tid] : 0;
    s[tid] = v; __syncthreads();
    for (int off = 1; off < 128; off <<= 1) {
        int t = (tid >= off) ? s[tid - off] : 0;
        __syncthreads();
        s[tid] += t;
        __syncthreads();
    }
    if (tid < NSB) g_boff[tid] = s[tid] - v;
}
__global__ void scan3_kernel() {                  // <<<NSB,1024>>>
    int i = blockIdx.x * 1024 + threadIdx.x;
    if (i < NN) {
        int v = g_off[i] + g_boff[blockIdx.x];
        g_off[i] = v;
        g_cursor[i] = v;
    }
    if (i == 0) g_off[NN] = NE;
}
__global__ void csr_scatter_kernel(const int* __restrict__ ei) {
    int e = blockIdx.x * 256 + threadIdx.x;
    if (e < NE) {
        int s = ei[e];
        int d = ei[NE + e];
        int p = atomicAdd(&g_cursor[d], 1);
        g_srcs[p] = s;
    }
}

// ---------------- gemm_pre: y = X @ W1_0 (F=128 -> 64), bf16 weights, bf16 store ----------------
// block = 64 nodes, 8 warps; warp = 8 nodes x 64 ch
__global__ void __launch_bounds__(256) gemm_pre_kernel(
    const float* __restrict__ X, const float* __restrict__ W, int N)
{
    constexpr int F = 128;
    __shared__ float xs[F * 68];            // [k][node], stride 68
    __shared__ unsigned wsb[F * 32];        // bf16x2 weights [k][cpair]
    int tid = threadIdx.x;

    const float2* Wv = (const float2*)W;
    #pragma unroll
    for (int i = tid; i < F * 32; i += 256) {
        float2 w = Wv[i];
        wsb[i] = bf16x2_pack(w.x, w.y);
    }

    int base = blockIdx.x * 64;
    int n = tid & 63, q0 = tid >> 6;
    int row = base + n;
    const float4* Xv = (const float4*)X;
    #pragma unroll
    for (int q = q0; q < F / 4; q += 4) {
        float4 v = make_float4(0.f, 0.f, 0.f, 0.f);
        if (row < N) v = Xv[row * (F / 4) + q];
        xs[(4 * q + 0) * 68 + n] = v.x;
        xs[(4 * q + 1) * 68 + n] = v.y;
        xs[(4 * q + 2) * 68 + n] = v.z;
        xs[(4 * q + 3) * 68 + n] = v.w;
    }
    __syncthreads();

    int w8 = (tid >> 5) * 8;
    int cp = tid & 31;
    unsigned long long acc[4][2];
    #pragma unroll
    for (int p = 0; p < 4; p++) { acc[p][0] = 0ull; acc[p][1] = 0ull; }
    #pragma unroll 4
    for (int k = 0; k < F; k++) {
        ulonglong2 xa = *(const ulonglong2*)&xs[k * 68 + w8];
        ulonglong2 xb = *(const ulonglong2*)&xs[k * 68 + w8 + 4];
        unsigned long long wx, wy;
        wpair_from_bf16x2(wsb[k * 32 + cp], wx, wy);
        f32x2_fma(acc[0][0], xa.x, wx); f32x2_fma(acc[0][1], xa.x, wy);
        f32x2_fma(acc[1][0], xa.y, wx); f32x2_fma(acc[1][1], xa.y, wy);
        f32x2_fma(acc[2][0], xb.x, wx); f32x2_fma(acc[2][1], xb.x, wy);
        f32x2_fma(acc[3][0], xb.y, wx); f32x2_fma(acc[3][1], xb.y, wy);
    }
    #pragma unroll
    for (int p = 0; p < 4; p++) {
        float2 u0 = f32x2_unpack(acc[p][0]);
        float2 u1 = f32x2_unpack(acc[p][1]);
        int r0 = base + w8 + 2 * p, r1 = r0 + 1;
        if (r0 < N) g_yb[r0 * 32 + cp] = __floats2bfloat162_rn(u0.x, u1.x);
        if (r1 < N) g_yb[r1 * 32 + cp] = __floats2bfloat162_rn(u0.y, u1.y);
    }
}

// ---------------- aggregate v2: 4 nodes/warp (8-lane quarters, 8 ch/lane) ----------------
// t[n] = (1+eps)*y[n] + sum_nb y + b1; fused BN stats
__global__ void __launch_bounds__(256) aggregate_kernel(
    const float* __restrict__ eps_arr, int layer, const float* __restrict__ b1)
{
    __shared__ float ss[128];
    int tid = threadIdx.x;
    if (tid < 128) ss[tid] = 0.f;
    __syncthreads();

    int warp = tid >> 5, lane = tid & 31;
    int q = lane >> 3, sl = lane & 7;
    int node = (blockIdx.x * 8 + warp) * 4 + q;
    unsigned qmask = 0xFFu << (q * 8);

    if (node < NN) {
        float oe = 1.0f + __ldg(&eps_arr[layer]);
        const uint4* Y4 = (const uint4*)g_yb;    // 16B = 8 channels (4x bf16x2)

        uint4 d = Y4[node * 8 + sl];
        float2 f0 = __bfloat1622float2(*(__nv_bfloat162*)&d.x);
        float2 f1 = __bfloat1622float2(*(__nv_bfloat162*)&d.y);
        float2 f2 = __bfloat1622float2(*(__nv_bfloat162*)&d.z);
        float2 f3 = __bfloat1622float2(*(__nv_bfloat162*)&d.w);
        float a0 = oe * f0.x, a1 = oe * f0.y, a2 = oe * f1.x, a3 = oe * f1.y;
        float a4 = oe * f2.x, a5 = oe * f2.y, a6 = oe * f3.x, a7 = oe * f3.y;

        int beg = g_off[node], end = g_off[node + 1];
        for (int bse = beg; bse < end; bse += 8) {
            int m = end - bse; if (m > 8) m = 8;
            int idx = (sl < m) ? g_srcs[bse + sl] : 0;
            #pragma unroll 4
            for (int t = 0; t < m; t++) {
                int s = __shfl_sync(qmask, idx, q * 8 + t);
                uint4 e = Y4[s * 8 + sl];
                float2 g0 = __bfloat1622float2(*(__nv_bfloat162*)&e.x);
                float2 g1 = __bfloat1622float2(*(__nv_bfloat162*)&e.y);
                float2 g2 = __bfloat1622float2(*(__nv_bfloat162*)&e.z);
                float2 g3 = __bfloat1622float2(*(__nv_bfloat162*)&e.w);
                a0 += g0.x; a1 += g0.y; a2 += g1.x; a3 += g1.y;
                a4 += g2.x; a5 += g2.y; a6 += g3.x; a7 += g3.y;
            }
        }
        float4 bb0 = __ldg((const float4*)&b1[sl * 8]);
        float4 bb1 = __ldg((const float4*)&b1[sl * 8 + 4]);
        a0 += bb0.x; a1 += bb0.y; a2 += bb0.z; a3 += bb0.w;
        a4 += bb1.x; a5 += bb1.y; a6 += bb1.z; a7 += bb1.w;

        float* tp = &g_t[node * 64 + sl * 8];
        *(float4*)tp       = make_float4(a0, a1, a2, a3);
        *(float4*)(tp + 4) = make_float4(a4, a5, a6, a7);

        int cb = sl * 8;
        atomicAdd(&ss[cb + 0], a0); atomicAdd(&ss[cb + 1], a1);
        atomicAdd(&ss[cb + 2], a2); atomicAdd(&ss[cb + 3], a3);
        atomicAdd(&ss[cb + 4], a4); atomicAdd(&ss[cb + 5], a5);
        atomicAdd(&ss[cb + 6], a6); atomicAdd(&ss[cb + 7], a7);
        atomicAdd(&ss[64 + cb + 0], a0 * a0); atomicAdd(&ss[64 + cb + 1], a1 * a1);
        atomicAdd(&ss[64 + cb + 2], a2 * a2); atomicAdd(&ss[64 + cb + 3], a3 * a3);
        atomicAdd(&ss[64 + cb + 4], a4 * a4); atomicAdd(&ss[64 + cb + 5], a5 * a5);
        atomicAdd(&ss[64 + cb + 6], a6 * a6); atomicAdd(&ss[64 + cb + 7], a7 * a7);
    }
    __syncthreads();
    if (tid < 128) atomicAdd(&g_stats[layer * 128 + tid], ss[tid]);
}

// ---------------- gemm_dual: z=relu(bn(t)); H=relu(z@W2+b2); pool H; y_next=H@W1n (bf16) ----------------
// block = 128 nodes, 8 warps; warp = 16 nodes x 64 ch; bf16 weights in smem
__global__ void __launch_bounds__(256) gemm_dual_kernel(
    const float* __restrict__ W2, const float* __restrict__ B2,
    const int* __restrict__ batch, int pool_off,
    const float* __restrict__ W1n, int has_next, int N,
    int layer, const float* __restrict__ gg, const float* __restrict__ be, float ninv)
{
    __shared__ float xs[64 * 132];          // [k][node], stride 132
    __shared__ unsigned ws2b[64 * 32];      // bf16x2 [k][cpair]
    __shared__ unsigned ws1b[64 * 32];
    __shared__ float scs[64], shs[64];
    int tid = threadIdx.x;

    {
        const float2* Wv = (const float2*)W2;
        #pragma unroll
        for (int i = tid; i < 2048; i += 256) {
            float2 w = Wv[i];
            ws2b[i] = bf16x2_pack(w.x, w.y);
        }
    }
    if (has_next) {
        const float2* Wv = (const float2*)W1n;
        #pragma unroll
        for (int i = tid; i < 2048; i += 256) {
            float2 w = Wv[i];
            ws1b[i] = bf16x2_pack(w.x, w.y);
        }
    }
    if (tid < 64) {
        float mean = g_stats[layer * 128 + tid] * ninv;
        float var  = g_stats[layer * 128 + 64 + tid] * ninv - mean * mean;
        float s = gg[tid] * rsqrtf(var + 1e-5f);
        scs[tid] = s;
        shs[tid] = fmaf(-mean, s, be[tid]);
    }
    __syncthreads();

    int base = blockIdx.x * 128;
    int n = tid & 127, q0 = tid >> 7;
    int row = base + n;
    const float4* Tv = (const float4*)g_t;
    #pragma unroll
    for (int q = q0; q < 16; q += 2) {
        float4 v = make_float4(0.f, 0.f, 0.f, 0.f);
        if (row < N) {
            float4 t = Tv[row * 16 + q];
            int cb = q * 4;
            v.x = fmaxf(fmaf(t.x, scs[cb + 0], shs[cb + 0]), 0.f);
            v.y = fmaxf(fmaf(t.y, scs[cb + 1], shs[cb + 1]), 0.f);
            v.z = fmaxf(fmaf(t.z, scs[cb + 2], shs[cb + 2]), 0.f);
            v.w = fmaxf(fmaf(t.w, scs[cb + 3], shs[cb + 3]), 0.f);
        }
        xs[(4 * q + 0) * 132 + n] = v.x;
        xs[(4 * q + 1) * 132 + n] = v.y;
        xs[(4 * q + 2) * 132 + n] = v.z;
        xs[(4 * q + 3) * 132 + n] = v.w;
    }
    __syncthreads();

    int w16 = (tid >> 5) * 16;
    int cp = tid & 31;
    int c = cp * 2;
    float2 bb = *(const float2*)&B2[c];
    unsigned long long acc[8][2];
    #pragma unroll
    for (int p = 0; p < 8; p++) { acc[p][0] = f32x2_dup(bb.x); acc[p][1] = f32x2_dup(bb.y); }
    #pragma unroll 4
    for (int k = 0; k < 64; k++) {
        ulonglong2 xa = *(const ulonglong2*)&xs[k * 132 + w16];
        ulonglong2 xb = *(const ulonglong2*)&xs[k * 132 + w16 + 4];
        ulonglong2 xc = *(const ulonglong2*)&xs[k * 132 + w16 + 8];
        ulonglong2 xd = *(const ulonglong2*)&xs[k * 132 + w16 + 12];
        unsigned long long wx, wy;
        wpair_from_bf16x2(ws2b[k * 32 + cp], wx, wy);
        f32x2_fma(acc[0][0], xa.x, wx); f32x2_fma(acc[0][1], xa.x, wy);
        f32x2_fma(acc[1][0], xa.y, wx); f32x2_fma(acc[1][1], xa.y, wy);
        f32x2_fma(acc[2][0], xb.x, wx); f32x2_fma(acc[2][1], xb.x, wy);
        f32x2_fma(acc[3][0], xb.y, wx); f32x2_fma(acc[3][1], xb.y, wy);
        f32x2_fma(acc[4][0], xc.x, wx); f32x2_fma(acc[4][1], xc.x, wy);
        f32x2_fma(acc[5][0], xc.y, wx); f32x2_fma(acc[5][1], xc.y, wy);
        f32x2_fma(acc[6][0], xd.x, wx); f32x2_fma(acc[6][1], xd.x, wy);
        f32x2_fma(acc[7][0], xd.y, wx); f32x2_fma(acc[7][1], xd.y, wy);
    }
    float H[16][2];
    #pragma unroll
    for (int p = 0; p < 8; p++) {
        float2 u0 = f32x2_unpack(acc[p][0]);
        float2 u1 = f32x2_unpack(acc[p][1]);
        H[2 * p + 0][0] = fmaxf(u0.x, 0.f); H[2 * p + 0][1] = fmaxf(u1.x, 0.f);
        H[2 * p + 1][0] = fmaxf(u0.y, 0.f); H[2 * p + 1][1] = fmaxf(u1.y, 0.f);
    }

    // pooling (batch sorted -> run-compressed atomics)
    int rbase = base + w16;
    int bprev = -1; float p0 = 0.f, p1 = 0.f;
    #pragma unroll
    for (int j = 0; j < 16; j++) {
        int r = rbase + j;
        if (r < N) {
            int bg = batch[r];
            if (bg != bprev) {
                if (bprev >= 0)
                    atomicAdd((float2*)&g_pooled[bprev * 256 + pool_off + c], make_float2(p0, p1));
                bprev = bg; p0 = 0.f; p1 = 0.f;
            }
            p0 += H[j][0]; p1 += H[j][1];
        }
    }
    if (bprev >= 0)
        atomicAdd((float2*)&g_pooled[bprev * 256 + pool_off + c], make_float2(p0, p1));

    if (has_next) {
        #pragma unroll
        for (int p = 0; p < 8; p++) {
            *(float2*)&xs[c * 132 + w16 + 2 * p]       = make_float2(H[2 * p][0], H[2 * p + 1][0]);
            *(float2*)&xs[(c + 1) * 132 + w16 + 2 * p] = make_float2(H[2 * p][1], H[2 * p + 1][1]);
        }
        __syncwarp();
        unsigned long long acc2[8][2];
        #pragma unroll
        for (int p = 0; p < 8; p++) { acc2[p][0] = 0ull; acc2[p][1] = 0ull; }
        #pragma unroll 4
        for (int k = 0; k < 64; k++) {
            ulonglong2 xa = *(const ulonglong2*)&xs[k * 132 + w16];
            ulonglong2 xb = *(const ulonglong2*)&xs[k * 132 + w16 + 4];
            ulonglong2 xc = *(const ulonglong2*)&xs[k * 132 + w16 + 8];
            ulonglong2 xd = *(const ulonglong2*)&xs[k * 132 + w16 + 12];
            unsigned long long wx, wy;
            wpair_from_bf16x2(ws1b[k * 32 + cp], wx, wy);
            f32x2_fma(acc2[0][0], xa.x, wx); f32x2_fma(acc2[0][1], xa.x, wy);
            f32x2_fma(acc2[1][0], xa.y, wx); f32x2_fma(acc2[1][1], xa.y, wy);
            f32x2_fma(acc2[2][0], xb.x, wx); f32x2_fma(acc2[2][1], xb.x, wy);
            f32x2_fma(acc2[3][0], xb.y, wx); f32x2_fma(acc2[3][1], xb.y, wy);
            f32x2_fma(acc2[4][0], xc.x, wx); f32x2_fma(acc2[4][1], xc.x, wy);
            f32x2_fma(acc2[5][0], xc.y, wx); f32x2_fma(acc2[5][1], xc.y, wy);
            f32x2_fma(acc2[6][0], xd.x, wx); f32x2_fma(acc2[6][1], xd.x, wy);
            f32x2_fma(acc2[7][0], xd.y, wx); f32x2_fma(acc2[7][1], xd.y, wy);
        }
        #pragma unroll
        for (int p = 0; p < 8; p++) {
            float2 u0 = f32x2_unpack(acc2[p][0]);
            float2 u1 = f32x2_unpack(acc2[p][1]);
            int r0 = rbase + 2 * p, r1 = r0 + 1;
            if (r0 < N) g_yb[r0 * 32 + cp] = __floats2bfloat162_rn(u0.x, u1.x);
            if (r1 < N) g_yb[r1 * 32 + cp] = __floats2bfloat162_rn(u0.y, u1.y);
        }
    }
}

// ---------------- head ----------------
__global__ void head1_kernel(const float* __restrict__ W, const float* __restrict__ B)
{
    int gph = blockIdx.x, c = threadIdx.x;   // <<<512,64>>>
    __shared__ float xs[256];
    #pragma unroll
    for (int i = c; i < 256; i += 64) xs[i] = g_pooled[gph * 256 + i];
    __syncthreads();
    float a = B[c];
    #pragma unroll 4
    for (int k = 0; k < 256; k++) a = fmaf(xs[k], __ldg(&W[k * 64 + c]), a);
    g_head1[gph * 64 + c] = a;
}

__global__ void head_bn_kernel(const float* __restrict__ g, const float* __restrict__ be)
{
    int c = blockIdx.x; int t = threadIdx.x;  // <<<64,256>>>
    __shared__ float red[256];
    float v0 = g_head1[t * 64 + c];
    float v1 = g_head1[(t + 256) * 64 + c];
    red[t] = v0 + v1;
    __syncthreads();
    for (int o = 128; o > 0; o >>= 1) { if (t < o) red[t] += red[t + o]; __syncthreads(); }
    float mean = red[0] * (1.0f / 512.0f);
    __syncthreads();
    float d0 = v0 - mean, d1 = v1 - mean;
    red[t] = d0 * d0 + d1 * d1;
    __syncthreads();
    for (int o = 128; o > 0; o >>= 1) { if (t < o) red[t] += red[t + o]; __syncthreads(); }
    if (t == 0) {
        float var = red[0] * (1.0f / 512.0f);
        float s = g[c] * rsqrtf(var + 1e-5f);
        g_scale[c] = s;
        g_shift[c] = fmaf(-mean, s, be[c]);
    }
}

__global__ void head_final_kernel(const float* __restrict__ W, const float* __restrict__ B,
                                  float* __restrict__ out)
{
    int gph = blockIdx.x; int c = threadIdx.x;   // <<<512,64>>>
    __shared__ float hn[64];
    __shared__ float logits[10];
    hn[c] = fmaxf(fmaf(g_head1[gph * 64 + c], g_scale[c], g_shift[c]), 0.f);
    __syncthreads();
    if (c < 10) {
        float a = B[c];
        #pragma unroll
        for (int k = 0; k < 64; k++) a = fmaf(hn[k], W[k * 10 + c], a);
        logits[c] = a;
    }
    __syncthreads();
    if (c == 0) {
        float m = logits[0];
        #pragma unroll
        for (int j = 1; j < 10; j++) m = fmaxf(m, logits[j]);
        float ssum = 0.f;
        #pragma unroll
        for (int j = 0; j < 10; j++) ssum += expf(logits[j] - m);
        float lse = m + logf(ssum);
        #pragma unroll
        for (int j = 0; j < 10; j++) out[gph * 10 + j] = logits[j] - lse;
    }
}

// ---------------- launch ----------------
extern "C" void kernel_launch(void* const* d_in, const int* in_sizes, int n_in,
                              void* d_out, int out_size)
{
    const float* x     = (const float*)d_in[0];
    const int*   ei    = (const int*)d_in[1];
    const int*   batch = (const int*)d_in[2];
    const float* eps   = (const float*)d_in[3];

    zero_all_kernel<<<(ZW + 255) / 256, 256>>>();                 // 1
    hist_kernel<<<(NE + 255) / 256, 256>>>(ei);                   // 2
    scan1_kernel<<<NSB, 1024>>>();                                // 3
    // gemm_pre independent of the scans -> profiled slot 4
    gemm_pre_kernel<<<(NN + 63) / 64, 256>>>(x, (const float*)d_in[4], NN);  // 4
    scan2_kernel<<<1, 128>>>();                                   // 5
    scan3_kernel<<<NSB, 1024>>>();                                // 6
    csr_scatter_kernel<<<(NE + 255) / 256, 256>>>(ei);            // 7

    for (int l = 0; l < 4; l++) {
        const float *b1, *gg, *be, *W2, *b2;
        if (l == 0) {
            b1 = (const float*)d_in[5];
            gg = (const float*)d_in[6]; be = (const float*)d_in[7];
            W2 = (const float*)d_in[8]; b2 = (const float*)d_in[9];
        } else {
            int j = l - 1;
            b1 = (const float*)d_in[11] + j * 64;
            gg = (const float*)d_in[12] + j * 64; be = (const float*)d_in[13] + j * 64;
            W2 = (const float*)d_in[14] + j * 64 * 64; b2 = (const float*)d_in[15] + j * 64;
        }
        const float* W1n = (l < 3) ? ((const float*)d_in[10] + l * 64 * 64) : (const float*)d_in[10];
        int has_next = (l < 3) ? 1 : 0;

        aggregate_kernel<<<(NN + 31) / 32, 256>>>(eps, l, b1);
        gemm_dual_kernel<<<(NN + 127) / 128, 256>>>(W2, b2, batch, l * 64, W1n, has_next, NN,
                                                    l, gg, be, 1.0f / (float)NN);
    }

    head1_kernel<<<NG, 64>>>((const float*)d_in[16], (const float*)d_in[17]);
    head_bn_kernel<<<64, 256>>>((const float*)d_in[18], (const float*)d_in[19]);
    head_final_kernel<<<NG, 64>>>((const float*)d_in[20], (const float*)d_in[21], (float*)d_out);
}

// round 10
// speedup vs baseline: 1.9045x; 1.9045x over previous
#include <cuda_runtime.h>
#include <cuda_bf16.h>
#include <math.h>

#define NN 100000
#define NE 1600000
#define NG 512
#define NSB 98   // scan blocks of 1024 -> covers 100352 >= NN

// ---------------- device scratch ----------------
__device__ __align__(256) __nv_bfloat162 g_yb[NN * 32];  // y in bf16x2: 128B/node
__device__ __align__(256) float g_t[NN * 64];
__device__ float g_stats[4 * 128];
__device__ float g_scale[64];
__device__ float g_shift[64];
__device__ float g_pooled[NG * 256];
__device__ float g_head1[NG * 64];
__device__ int   g_deg[NN];
__device__ int   g_off[NN + 1];
__device__ int   g_cursor[NN];
__device__ int   g_srcs[NE];
__device__ int   g_bsum[NSB];
__device__ int   g_boff[NSB];

// ---------------- f32x2 helpers (FFMA2 path, gemm_pre) ----------------
__device__ __forceinline__ unsigned long long f32x2_dup(float x) {
    unsigned long long r;
    asm("mov.b64 %0, {%1, %1};" : "=l"(r) : "f"(x));
    return r;
}
__device__ __forceinline__ void f32x2_fma(unsigned long long &d,
                                          unsigned long long a, unsigned long long b) {
    asm("fma.rn.f32x2 %0, %1, %2, %0;" : "+l"(d) : "l"(a), "l"(b));
}
__device__ __forceinline__ float2 f32x2_unpack(unsigned long long v) {
    float2 r;
    asm("mov.b64 {%0, %1}, %2;" : "=f"(r.x), "=f"(r.y) : "l"(v));
    return r;
}

// ---------------- tf32 mma helpers ----------------
__device__ __forceinline__ unsigned tf32_cvt(float x) {
    unsigned r;
    asm("cvt.rna.tf32.f32 %0, %1;" : "=r"(r) : "f"(x));
    return r;
}
__device__ __forceinline__ void mma_tf32(float* d,
                                         unsigned a0, unsigned a1, unsigned a2, unsigned a3,
                                         unsigned b0, unsigned b1) {
    asm("mma.sync.aligned.m16n8k8.row.col.f32.tf32.tf32.f32 "
        "{%0,%1,%2,%3}, {%4,%5,%6,%7}, {%8,%9}, {%0,%1,%2,%3};"
        : "+f"(d[0]), "+f"(d[1]), "+f"(d[2]), "+f"(d[3])
        : "r"(a0), "r"(a1), "r"(a2), "r"(a3), "r"(b0), "r"(b1));
}

// ---------------- fused zero kernel ----------------
#define ZW (131072 + 512 + NN)
__global__ void zero_all_kernel() {
    int i = blockIdx.x * 256 + threadIdx.x;
    if (i < 131072) g_pooled[i] = 0.f;
    else if (i < 131072 + 512) g_stats[i - 131072] = 0.f;
    else if (i < ZW) g_deg[i - 131072 - 512] = 0;
}

// ---------------- CSR build ----------------
__global__ void hist_kernel(const int* __restrict__ ei) {
    int e = blockIdx.x * 256 + threadIdx.x;
    if (e < NE) atomicAdd(&g_deg[ei[NE + e]], 1);
}
__global__ void scan1_kernel() {                  // <<<NSB,1024>>>
    __shared__ int wsum[32];
    int tid = threadIdx.x;
    int i = blockIdx.x * 1024 + tid;
    int v = (i < NN) ? g_deg[i] : 0;
    int x = v;
    #pragma unroll
    for (int o = 1; o < 32; o <<= 1) {
        int t = __shfl_up_sync(0xffffffffu, x, o);
        if ((tid & 31) >= o) x += t;
    }
    if ((tid & 31) == 31) wsum[tid >> 5] = x;
    __syncthreads();
    if (tid < 32) {
        int y = wsum[tid];
        #pragma unroll
        for (int o = 1; o < 32; o <<= 1) {
            int t = __shfl_up_sync(0xffffffffu, y, o);
            if (tid >= o) y += t;
        }
        wsum[tid] = y;
    }
    __syncthreads();
    int base = (tid >= 32) ? wsum[(tid >> 5) - 1] : 0;
    int incl = x + base;
    if (i < NN) g_off[i] = incl - v;
    if (tid == 1023) g_bsum[blockIdx.x] = incl;
}
__global__ void scan2_kernel() {                  // <<<1,128>>>
    __shared__ int s[128];
    int tid = threadIdx.x;
    int v = (tid < NSB) ? g_bsum[tid] : 0;
    s[tid] = v; __syncthreads();
    for (int off = 1; off < 128; off <<= 1) {
        int t = (tid >= off) ? s[tid - off] : 0;
        __syncthreads();
        s[tid] += t;
        __syncthreads();
    }
    if (tid < NSB) g_boff[tid] = s[tid] - v;
}
__global__ void scan3_kernel() {                  // <<<NSB,1024>>>
    int i = blockIdx.x * 1024 + threadIdx.x;
    if (i < NN) {
        int v = g_off[i] + g_boff[blockIdx.x];
        g_off[i] = v;
        g_cursor[i] = v;
    }
    if (i == 0) g_off[NN] = NE;
}
__global__ void csr_scatter_kernel(const int* __restrict__ ei) {
    int e = blockIdx.x * 256 + threadIdx.x;
    if (e < NE) {
        int s = ei[e];
        int d = ei[NE + e];
        int p = atomicAdd(&g_cursor[d], 1);
        g_srcs[p] = s;
    }
}

// ---------------- gemm_pre: y = X @ W1_0 (F=128 -> 64), fp32 FFMA2, bf16 store ----------------
// block = 64 nodes, 8 warps; warp = 8 nodes x 64 ch (round-7 version)
__global__ void __launch_bounds__(256) gemm_pre_kernel(
    const float* __restrict__ X, const float* __restrict__ W, int N)
{
    constexpr int F = 128;
    __shared__ float xs[F * 68];
    __shared__ float ws[F * 64];
    int tid = threadIdx.x;

    const float4* Wv = (const float4*)W;
    float4* wsv = (float4*)ws;
    #pragma unroll
    for (int i = tid; i < F * 16; i += 256) wsv[i] = Wv[i];

    int base = blockIdx.x * 64;
    int n = tid & 63, q0 = tid >> 6;
    int row = base + n;
    const float4* Xv = (const float4*)X;
    #pragma unroll
    for (int q = q0; q < F / 4; q += 4) {
        float4 v = make_float4(0.f, 0.f, 0.f, 0.f);
        if (row < N) v = Xv[row * (F / 4) + q];
        xs[(4 * q + 0) * 68 + n] = v.x;
        xs[(4 * q + 1) * 68 + n] = v.y;
        xs[(4 * q + 2) * 68 + n] = v.z;
        xs[(4 * q + 3) * 68 + n] = v.w;
    }
    __syncthreads();

    int w8 = (tid >> 5) * 8;
    int cp = tid & 31;
    int c = cp * 2;
    unsigned long long acc[4][2];
    #pragma unroll
    for (int p = 0; p < 4; p++) { acc[p][0] = 0ull; acc[p][1] = 0ull; }
    #pragma unroll 4
    for (int k = 0; k < F; k++) {
        ulonglong2 xa = *(const ulonglong2*)&xs[k * 68 + w8];
        ulonglong2 xb = *(const ulonglong2*)&xs[k * 68 + w8 + 4];
        float2 wv = *(const float2*)&ws[k * 64 + c];
        unsigned long long wx = f32x2_dup(wv.x), wy = f32x2_dup(wv.y);
        f32x2_fma(acc[0][0], xa.x, wx); f32x2_fma(acc[0][1], xa.x, wy);
        f32x2_fma(acc[1][0], xa.y, wx); f32x2_fma(acc[1][1], xa.y, wy);
        f32x2_fma(acc[2][0], xb.x, wx); f32x2_fma(acc[2][1], xb.x, wy);
        f32x2_fma(acc[3][0], xb.y, wx); f32x2_fma(acc[3][1], xb.y, wy);
    }
    #pragma unroll
    for (int p = 0; p < 4; p++) {
        float2 u0 = f32x2_unpack(acc[p][0]);
        float2 u1 = f32x2_unpack(acc[p][1]);
        int r0 = base + w8 + 2 * p, r1 = r0 + 1;
        if (r0 < N) g_yb[r0 * 32 + cp] = __floats2bfloat162_rn(u0.x, u1.x);
        if (r1 < N) g_yb[r1 * 32 + cp] = __floats2bfloat162_rn(u0.y, u1.y);
    }
}

// ---------------- aggregate (round-7): warp/node, t = (1+eps)y + gather(y) + b1; BN stats ----------------
__global__ void __launch_bounds__(256) aggregate_kernel(
    const float* __restrict__ eps_arr, int layer, const float* __restrict__ b1)
{
    __shared__ float ss[128];
    int tid = threadIdx.x;
    if (tid < 128) ss[tid] = 0.f;
    __syncthreads();

    int warp = (blockIdx.x * 256 + tid) >> 5;
    int lane = tid & 31;
    if (warp < NN) {
        float oe = 1.0f + __ldg(&eps_arr[layer]);
        int beg = g_off[warp], end = g_off[warp + 1];
        float2 self = __bfloat1622float2(g_yb[warp * 32 + lane]);
        float2 acc = make_float2(self.x * oe, self.y * oe);
        for (int bse = beg; bse < end; bse += 32) {
            int m = end - bse; if (m > 32) m = 32;
            int idx = (lane < m) ? g_srcs[bse + lane] : 0;
            int t = 0;
            for (; t + 4 <= m; t += 4) {
                int s0 = __shfl_sync(0xffffffffu, idx, t);
                int s1 = __shfl_sync(0xffffffffu, idx, t + 1);
                int s2 = __shfl_sync(0xffffffffu, idx, t + 2);
                int s3 = __shfl_sync(0xffffffffu, idx, t + 3);
                float2 a = __bfloat1622float2(g_yb[s0 * 32 + lane]);
                float2 b = __bfloat1622float2(g_yb[s1 * 32 + lane]);
                float2 cc = __bfloat1622float2(g_yb[s2 * 32 + lane]);
                float2 d = __bfloat1622float2(g_yb[s3 * 32 + lane]);
                acc.x += (a.x + b.x) + (cc.x + d.x);
                acc.y += (a.y + b.y) + (cc.y + d.y);
            }
            for (; t < m; t++) {
                int s0 = __shfl_sync(0xffffffffu, idx, t);
                float2 a = __bfloat1622float2(g_yb[s0 * 32 + lane]);
                acc.x += a.x; acc.y += a.y;
            }
        }
        float2 bb = *(const float2*)&b1[2 * lane];
        acc.x += bb.x; acc.y += bb.y;
        *(float2*)&g_t[warp * 64 + 2 * lane] = acc;
        atomicAdd(&ss[2 * lane], acc.x);
        atomicAdd(&ss[2 * lane + 1], acc.y);
        atomicAdd(&ss[64 + 2 * lane], acc.x * acc.x);
        atomicAdd(&ss[64 + 2 * lane + 1], acc.y * acc.y);
    }
    __syncthreads();
    if (tid < 128) atomicAdd(&g_stats[layer * 128 + tid], ss[tid]);
}

// ---------------- gemm_dual (TF32 mma.sync): z=relu(bn(t)); H=relu(z@W2+b2);
//                  y_next = H@W1n (bf16 out); pool H ----------------
// block = 128 nodes, 8 warps; warp = 16-row m-tile x 64 cols (8 n-tiles), K=64 (8 k-steps)
__global__ void __launch_bounds__(256) gemm_dual_kernel(
    const float* __restrict__ W2, const float* __restrict__ B2,
    const int* __restrict__ batch, int pool_off,
    const float* __restrict__ W1n, int has_next, int N,
    int layer, const float* __restrict__ gg, const float* __restrict__ be, float ninv)
{
    __shared__ float sA[128 * 68];    // A (z, tf32 bits) -> reused for H (f32)
    __shared__ float sB2[64 * 68];    // W2^T [n][k], tf32 bits
    __shared__ float sB1[64 * 68];    // W1n^T [n][k], tf32 bits
    __shared__ float scs[64], shs[64], b2s[64];
    int tid = threadIdx.x, wid = tid >> 5, lid = tid & 31;
    int gi = lid >> 2, ti = lid & 3;

    if (tid < 64) {
        float mean = g_stats[layer * 128 + tid] * ninv;
        float var  = g_stats[layer * 128 + 64 + tid] * ninv - mean * mean;
        float s = gg[tid] * rsqrtf(var + 1e-5f);
        scs[tid] = s;
        shs[tid] = fmaf(-mean, s, be[tid]);
        b2s[tid] = B2[tid];
    }
    __syncthreads();

    // stage A = tf32(relu(bn(g_t))): [row][k], stride 68
    int base = blockIdx.x * 128;
    #pragma unroll 2
    for (int i = tid; i < 2048; i += 256) {
        int row = i >> 4, u = i & 15;
        float4 v = make_float4(0.f, 0.f, 0.f, 0.f);
        int r = base + row;
        if (r < N) {
            float4 t = ((const float4*)g_t)[r * 16 + u];
            int cb = u * 4;
            v.x = fmaxf(fmaf(t.x, scs[cb + 0], shs[cb + 0]), 0.f);
            v.y = fmaxf(fmaf(t.y, scs[cb + 1], shs[cb + 1]), 0.f);
            v.z = fmaxf(fmaf(t.z, scs[cb + 2], shs[cb + 2]), 0.f);
            v.w = fmaxf(fmaf(t.w, scs[cb + 3], shs[cb + 3]), 0.f);
        }
        float* ap = &sA[row * 68 + u * 4];
        ap[0] = __uint_as_float(tf32_cvt(v.x));
        ap[1] = __uint_as_float(tf32_cvt(v.y));
        ap[2] = __uint_as_float(tf32_cvt(v.z));
        ap[3] = __uint_as_float(tf32_cvt(v.w));
    }
    // stage B2/B1 transposed: W[k][n] -> sB[n][k]
    #pragma unroll 2
    for (int i = tid; i < 4096; i += 256) {
        int k = i >> 6, n = i & 63;
        sB2[n * 68 + k] = __uint_as_float(tf32_cvt(W2[i]));
    }
    if (has_next) {
        #pragma unroll 2
        for (int i = tid; i < 4096; i += 256) {
            int k = i >> 6, n = i & 63;
            sB1[n * 68 + k] = __uint_as_float(tf32_cvt(W1n[i]));
        }
    }
    __syncthreads();

    // MMA1: D = A @ W2^T, bias pre-loaded into accumulators
    int arow = wid * 16 + gi;                 // rows arow (a0/a2) and arow+8 (a1/a3)
    float d[8][4];
    #pragma unroll
    for (int j = 0; j < 8; j++) {
        float bb0 = b2s[8 * j + 2 * ti], bb1 = b2s[8 * j + 2 * ti + 1];
        d[j][0] = bb0; d[j][1] = bb1; d[j][2] = bb0; d[j][3] = bb1;
    }
    #pragma unroll
    for (int t = 0; t < 8; t++) {
        int kb = t * 8;
        unsigned a0 = __float_as_uint(sA[arow * 68 + kb + ti]);
        unsigned a1 = __float_as_uint(sA[(arow + 8) * 68 + kb + ti]);
        unsigned a2 = __float_as_uint(sA[arow * 68 + kb + ti + 4]);
        unsigned a3 = __float_as_uint(sA[(arow + 8) * 68 + kb + ti + 4]);
        #pragma unroll
        for (int j = 0; j < 8; j++) {
            unsigned b0 = __float_as_uint(sB2[(8 * j + gi) * 68 + kb + ti]);
            unsigned b1 = __float_as_uint(sB2[(8 * j + gi) * 68 + kb + ti + 4]);
            mma_tf32(d[j], a0, a1, a2, a3, b0, b1);
        }
    }

    // H = relu(D); overwrite own-warp rows of sA (A fully consumed by this warp)
    #pragma unroll
    for (int j = 0; j < 8; j++) {
        float h0 = fmaxf(d[j][0], 0.f), h1 = fmaxf(d[j][1], 0.f);
        float h2 = fmaxf(d[j][2], 0.f), h3 = fmaxf(d[j][3], 0.f);
        *(float2*)&sA[arow * 68 + 8 * j + 2 * ti]       = make_float2(h0, h1);
        *(float2*)&sA[(arow + 8) * 68 + 8 * j + 2 * ti] = make_float2(h2, h3);
    }
    __syncwarp();

    // MMA2: y_next = H @ W1n^T (tf32), write bf16
    if (has_next) {
        float e[8][4];
        #pragma unroll
        for (int j = 0; j < 8; j++) { e[j][0] = 0.f; e[j][1] = 0.f; e[j][2] = 0.f; e[j][3] = 0.f; }
        #pragma unroll
        for (int t = 0; t < 8; t++) {
            int kb = t * 8;
            unsigned a0 = tf32_cvt(sA[arow * 68 + kb + ti]);
            unsigned a1 = tf32_cvt(sA[(arow + 8) * 68 + kb + ti]);
            unsigned a2 = tf32_cvt(sA[arow * 68 + kb + ti + 4]);
            unsigned a3 = tf32_cvt(sA[(arow + 8) * 68 + kb + ti + 4]);
            #pragma unroll
            for (int j = 0; j < 8; j++) {
                unsigned b0 = __float_as_uint(sB1[(8 * j + gi) * 68 + kb + ti]);
                unsigned b1 = __float_as_uint(sB1[(8 * j + gi) * 68 + kb + ti + 4]);
                mma_tf32(e[j], a0, a1, a2, a3, b0, b1);
            }
        }
        int r0 = base + arow, r1 = base + arow + 8;
        if (r0 < N) {
            #pragma unroll
            for (int j = 0; j < 8; j++)
                g_yb[r0 * 32 + 4 * j + ti] = __floats2bfloat162_rn(e[j][0], e[j][1]);
        }
        if (r1 < N) {
            #pragma unroll
            for (int j = 0; j < 8; j++)
                g_yb[r1 * 32 + 4 * j + ti] = __floats2bfloat162_rn(e[j][2], e[j][3]);
        }
    }

    // pooling from sA H (f32), run-compressed (batch sorted): warp rows wid*16..+15, lane = cpair
    {
        int prow = wid * 16;
        int cp = lid;
        int bprev = -1; float p0 = 0.f, p1 = 0.f;
        #pragma unroll
        for (int j = 0; j < 16; j++) {
            int rr = base + prow + j;
            if (rr < N) {
                float2 hv = *(const float2*)&sA[(prow + j) * 68 + 2 * cp];
                int bg = batch[rr];
                if (bg != bprev) {
                    if (bprev >= 0)
                        atomicAdd((float2*)&g_pooled[bprev * 256 + pool_off + 2 * cp],
                                  make_float2(p0, p1));
                    bprev = bg; p0 = 0.f; p1 = 0.f;
                }
                p0 += hv.x; p1 += hv.y;
            }
        }
        if (bprev >= 0)
            atomicAdd((float2*)&g_pooled[bprev * 256 + pool_off + 2 * cp],
                      make_float2(p0, p1));
    }
}

// ---------------- head ----------------
__global__ void head1_kernel(const float* __restrict__ W, const float* __restrict__ B)
{
    int gph = blockIdx.x, c = threadIdx.x;   // <<<512,64>>>
    __shared__ float xs[256];
    #pragma unroll
    for (int i = c; i < 256; i += 64) xs[i] = g_pooled[gph * 256 + i];
    __syncthreads();
    float a = B[c];
    #pragma unroll 4
    for (int k = 0; k < 256; k++) a = fmaf(xs[k], __ldg(&W[k * 64 + c]), a);
    g_head1[gph * 64 + c] = a;
}

__global__ void head_bn_kernel(const float* __restrict__ g, const float* __restrict__ be)
{
    int c = blockIdx.x; int t = threadIdx.x;  // <<<64,256>>>
    __shared__ float red[256];
    float v0 = g_head1[t * 64 + c];
    float v1 = g_head1[(t + 256) * 64 + c];
    red[t] = v0 + v1;
    __syncthreads();
    for (int o = 128; o > 0; o >>= 1) { if (t < o) red[t] += red[t + o]; __syncthreads(); }
    float mean = red[0] * (1.0f / 512.0f);
    __syncthreads();
    float d0 = v0 - mean, d1 = v1 - mean;
    red[t] = d0 * d0 + d1 * d1;
    __syncthreads();
    for (int o = 128; o > 0; o >>= 1) { if (t < o) red[t] += red[t + o]; __syncthreads(); }
    if (t == 0) {
        float var = red[0] * (1.0f / 512.0f);
        float s = g[c] * rsqrtf(var + 1e-5f);
        g_scale[c] = s;
        g_shift[c] = fmaf(-mean, s, be[c]);
    }
}

__global__ void head_final_kernel(const float* __restrict__ W, const float* __restrict__ B,
                                  float* __restrict__ out)
{
    int gph = blockIdx.x; int c = threadIdx.x;   // <<<512,64>>>
    __shared__ float hn[64];
    __shared__ float logits[10];
    hn[c] = fmaxf(fmaf(g_head1[gph * 64 + c], g_scale[c], g_shift[c]), 0.f);
    __syncthreads();
    if (c < 10) {
        float a = B[c];
        #pragma unroll
        for (int k = 0; k < 64; k++) a = fmaf(hn[k], W[k * 10 + c], a);
        logits[c] = a;
    }
    __syncthreads();
    if (c == 0) {
        float m = logits[0];
        #pragma unroll
        for (int j = 1; j < 10; j++) m = fmaxf(m, logits[j]);
        float ssum = 0.f;
        #pragma unroll
        for (int j = 0; j < 10; j++) ssum += expf(logits[j] - m);
        float lse = m + logf(ssum);
        #pragma unroll
        for (int j = 0; j < 10; j++) out[gph * 10 + j] = logits[j] - lse;
    }
}

// ---------------- launch ----------------
extern "C" void kernel_launch(void* const* d_in, const int* in_sizes, int n_in,
                              void* d_out, int out_size)
{
    const float* x     = (const float*)d_in[0];
    const int*   ei    = (const int*)d_in[1];
    const int*   batch = (const int*)d_in[2];
    const float* eps   = (const float*)d_in[3];

    zero_all_kernel<<<(ZW + 255) / 256, 256>>>();                 // 1
    hist_kernel<<<(NE + 255) / 256, 256>>>(ei);                   // 2
    scan1_kernel<<<NSB, 1024>>>();                                // 3
    gemm_pre_kernel<<<(NN + 63) / 64, 256>>>(x, (const float*)d_in[4], NN);  // 4 (profiled)
    scan2_kernel<<<1, 128>>>();                                   // 5
    scan3_kernel<<<NSB, 1024>>>();                                // 6
    csr_scatter_kernel<<<(NE + 255) / 256, 256>>>(ei);            // 7

    for (int l = 0; l < 4; l++) {
        const float *b1, *gg, *be, *W2, *b2;
        if (l == 0) {
            b1 = (const float*)d_in[5];
            gg = (const float*)d_in[6]; be = (const float*)d_in[7];
            W2 = (const float*)d_in[8]; b2 = (const float*)d_in[9];
        } else {
            int j = l - 1;
            b1 = (const float*)d_in[11] + j * 64;
            gg = (const float*)d_in[12] + j * 64; be = (const float*)d_in[13] + j * 64;
            W2 = (const float*)d_in[14] + j * 64 * 64; b2 = (const float*)d_in[15] + j * 64;
        }
        const float* W1n = (l < 3) ? ((const float*)d_in[10] + l * 64 * 64) : (const float*)d_in[10];
        int has_next = (l < 3) ? 1 : 0;

        aggregate_kernel<<<(NN * 32 + 255) / 256, 256>>>(eps, l, b1);
        gemm_dual_kernel<<<(NN + 127) / 128, 256>>>(W2, b2, batch, l * 64, W1n, has_next, NN,
                                                    l, gg, be, 1.0f / (float)NN);
    }

    head1_kernel<<<NG, 64>>>((const float*)d_in[16], (const float*)d_in[17]);
    head_bn_kernel<<<64, 256>>>((const float*)d_in[18], (const float*)d_in[19]);
    head_final_kernel<<<NG, 64>>>((const float*)d_in[20], (const float*)d_in[21], (float*)d_out);
}

// round 11
// speedup vs baseline: 2.0055x; 1.0530x over previous
#include <cuda_runtime.h>
#include <cuda_bf16.h>
#include <math.h>

#define NN 100000
#define NE 1600000
#define NG 512
#define NSB 98   // scan blocks of 1024 -> covers 100352 >= NN

// ---------------- device scratch ----------------
__device__ __align__(256) __nv_bfloat162 g_yb[NN * 32];  // y in bf16x2: 128B/node
__device__ __align__(256) float g_t[NN * 64];
__device__ float g_stats[4 * 128];
__device__ float g_scale[64];
__device__ float g_shift[64];
__device__ float g_pooled[NG * 256];
__device__ float g_head1[NG * 64];
__device__ int   g_deg[NN];
__device__ int   g_off[NN + 1];
__device__ int   g_cursor[NN];
__device__ int   g_srcs[NE];
__device__ int   g_bsum[NSB];
__device__ int   g_boff[NSB];

// ---------------- tf32 mma helpers ----------------
__device__ __forceinline__ unsigned tf32_cvt(float x) {
    unsigned r;
    asm("cvt.rna.tf32.f32 %0, %1;" : "=r"(r) : "f"(x));
    return r;
}
__device__ __forceinline__ void mma_tf32(float* d,
                                         unsigned a0, unsigned a1, unsigned a2, unsigned a3,
                                         unsigned b0, unsigned b1) {
    asm("mma.sync.aligned.m16n8k8.row.col.f32.tf32.tf32.f32 "
        "{%0,%1,%2,%3}, {%4,%5,%6,%7}, {%8,%9}, {%0,%1,%2,%3};"
        : "+f"(d[0]), "+f"(d[1]), "+f"(d[2]), "+f"(d[3])
        : "r"(a0), "r"(a1), "r"(a2), "r"(a3), "r"(b0), "r"(b1));
}

// ---------------- fused zero kernel ----------------
#define ZW (131072 + 512 + NN)
__global__ void zero_all_kernel() {
    int i = blockIdx.x * 256 + threadIdx.x;
    if (i < 131072) g_pooled[i] = 0.f;
    else if (i < 131072 + 512) g_stats[i - 131072] = 0.f;
    else if (i < ZW) g_deg[i - 131072 - 512] = 0;
}

// ---------------- CSR build ----------------
__global__ void hist_kernel(const int* __restrict__ ei) {
    int e = blockIdx.x * 256 + threadIdx.x;
    if (e < NE) atomicAdd(&g_deg[ei[NE + e]], 1);
}
__global__ void scan1_kernel() {                  // <<<NSB,1024>>>
    __shared__ int wsum[32];
    int tid = threadIdx.x;
    int i = blockIdx.x * 1024 + tid;
    int v = (i < NN) ? g_deg[i] : 0;
    int x = v;
    #pragma unroll
    for (int o = 1; o < 32; o <<= 1) {
        int t = __shfl_up_sync(0xffffffffu, x, o);
        if ((tid & 31) >= o) x += t;
    }
    if ((tid & 31) == 31) wsum[tid >> 5] = x;
    __syncthreads();
    if (tid < 32) {
        int y = wsum[tid];
        #pragma unroll
        for (int o = 1; o < 32; o <<= 1) {
            int t = __shfl_up_sync(0xffffffffu, y, o);
            if (tid >= o) y += t;
        }
        wsum[tid] = y;
    }
    __syncthreads();
    int base = (tid >= 32) ? wsum[(tid >> 5) - 1] : 0;
    int incl = x + base;
    if (i < NN) g_off[i] = incl - v;
    if (tid == 1023) g_bsum[blockIdx.x] = incl;
}
__global__ void scan2_kernel() {                  // <<<1,128>>>
    __shared__ int s[128];
    int tid = threadIdx.x;
    int v = (tid < NSB) ? g_bsum[tid] : 0;
    s[tid] = v; __syncthreads();
    for (int off = 1; off < 128; off <<= 1) {
        int t = (tid >= off) ? s[tid - off] : 0;
        __syncthreads();
        s[tid] += t;
        __syncthreads();
    }
    if (tid < NSB) g_boff[tid] = s[tid] - v;
}
__global__ void scan3_kernel() {                  // <<<NSB,1024>>>
    int i = blockIdx.x * 1024 + threadIdx.x;
    if (i < NN) {
        int v = g_off[i] + g_boff[blockIdx.x];
        g_off[i] = v;
        g_cursor[i] = v;
    }
    if (i == 0) g_off[NN] = NE;
}
__global__ void csr_scatter_kernel(const int* __restrict__ ei) {
    int e = blockIdx.x * 256 + threadIdx.x;
    if (e < NE) {
        int s = ei[e];
        int d = ei[NE + e];
        int p = atomicAdd(&g_cursor[d], 1);
        g_srcs[p] = s;
    }
}

// ---------------- gemm_pre (TF32 mma.sync): y = X @ W1_0 (K=128 -> 64), bf16 store ----------------
// block = 64 nodes, 4 warps (128 thr); warp = 16-row m-tile x 64 cols, K=128 (16 k-steps)
__global__ void __launch_bounds__(128) gemm_pre_kernel(
    const float* __restrict__ X, const float* __restrict__ W, int N)
{
    __shared__ float sX[64 * 132];    // tf32 bits [row][k], stride 132
    __shared__ float sW[64 * 132];    // W^T [n][k], tf32 bits
    int tid = threadIdx.x, wid = tid >> 5, lid = tid & 31;
    int gi = lid >> 2, ti = lid & 3;
    int base = blockIdx.x * 64;

    // stage X (tf32), STS.128 conflict-free
    const float4* Xv = (const float4*)X;
    #pragma unroll 4
    for (int i = tid; i < 64 * 32; i += 128) {
        int row = i >> 5, q = i & 31;
        float4 v = make_float4(0.f, 0.f, 0.f, 0.f);
        int r = base + row;
        if (r < N) v = Xv[r * 32 + q];
        float4 tv;
        tv.x = __uint_as_float(tf32_cvt(v.x));
        tv.y = __uint_as_float(tf32_cvt(v.y));
        tv.z = __uint_as_float(tf32_cvt(v.z));
        tv.w = __uint_as_float(tf32_cvt(v.w));
        *(float4*)&sX[row * 132 + q * 4] = tv;
    }
    // stage W^T: W[k][n] -> sW[n][k]
    #pragma unroll 8
    for (int i = tid; i < 128 * 64; i += 128) {
        int k = i >> 6, n = i & 63;
        sW[n * 132 + k] = __uint_as_float(tf32_cvt(W[i]));
    }
    __syncthreads();

    int arow = wid * 16 + gi;
    float e[8][4];
    #pragma unroll
    for (int j = 0; j < 8; j++) { e[j][0] = 0.f; e[j][1] = 0.f; e[j][2] = 0.f; e[j][3] = 0.f; }
    #pragma unroll
    for (int t = 0; t < 16; t++) {
        int kb = t * 8;
        unsigned a0 = __float_as_uint(sX[arow * 132 + kb + ti]);
        unsigned a1 = __float_as_uint(sX[(arow + 8) * 132 + kb + ti]);
        unsigned a2 = __float_as_uint(sX[arow * 132 + kb + ti + 4]);
        unsigned a3 = __float_as_uint(sX[(arow + 8) * 132 + kb + ti + 4]);
        #pragma unroll
        for (int j = 0; j < 8; j++) {
            unsigned b0 = __float_as_uint(sW[(8 * j + gi) * 132 + kb + ti]);
            unsigned b1 = __float_as_uint(sW[(8 * j + gi) * 132 + kb + ti + 4]);
            mma_tf32(e[j], a0, a1, a2, a3, b0, b1);
        }
    }
    // write y as bf16x2: lane (gi,ti) holds rows arow/arow+8, cols 8j+2ti, 8j+2ti+1
    int r0 = base + arow, r1 = base + arow + 8;
    if (r0 < N) {
        #pragma unroll
        for (int j = 0; j < 8; j++)
            g_yb[r0 * 32 + 4 * j + ti] = __floats2bfloat162_rn(e[j][0], e[j][1]);
    }
    if (r1 < N) {
        #pragma unroll
        for (int j = 0; j < 8; j++)
            g_yb[r1 * 32 + 4 * j + ti] = __floats2bfloat162_rn(e[j][2], e[j][3]);
    }
}

// ---------------- aggregate: warp/node, t = (1+eps)y + gather(y) + b1; BN stats ----------------
__global__ void __launch_bounds__(256) aggregate_kernel(
    const float* __restrict__ eps_arr, int layer, const float* __restrict__ b1)
{
    __shared__ float ss[128];
    int tid = threadIdx.x;
    if (tid < 128) ss[tid] = 0.f;
    __syncthreads();

    int warp = (blockIdx.x * 256 + tid) >> 5;
    int lane = tid & 31;
    if (warp < NN) {
        float oe = 1.0f + __ldg(&eps_arr[layer]);
        int beg = g_off[warp], end = g_off[warp + 1];
        float2 self = __bfloat1622float2(g_yb[warp * 32 + lane]);
        float2 acc = make_float2(self.x * oe, self.y * oe);
        for (int bse = beg; bse < end; bse += 32) {
            int m = end - bse; if (m > 32) m = 32;
            int idx = (lane < m) ? g_srcs[bse + lane] : 0;
            int t = 0;
            for (; t + 4 <= m; t += 4) {
                int s0 = __shfl_sync(0xffffffffu, idx, t);
                int s1 = __shfl_sync(0xffffffffu, idx, t + 1);
                int s2 = __shfl_sync(0xffffffffu, idx, t + 2);
                int s3 = __shfl_sync(0xffffffffu, idx, t + 3);
                float2 a = __bfloat1622float2(g_yb[s0 * 32 + lane]);
                float2 b = __bfloat1622float2(g_yb[s1 * 32 + lane]);
                float2 cc = __bfloat1622float2(g_yb[s2 * 32 + lane]);
                float2 d = __bfloat1622float2(g_yb[s3 * 32 + lane]);
                acc.x += (a.x + b.x) + (cc.x + d.x);
                acc.y += (a.y + b.y) + (cc.y + d.y);
            }
            for (; t < m; t++) {
                int s0 = __shfl_sync(0xffffffffu, idx, t);
                float2 a = __bfloat1622float2(g_yb[s0 * 32 + lane]);
                acc.x += a.x; acc.y += a.y;
            }
        }
        float2 bb = *(const float2*)&b1[2 * lane];
        acc.x += bb.x; acc.y += bb.y;
        *(float2*)&g_t[warp * 64 + 2 * lane] = acc;
        atomicAdd(&ss[2 * lane], acc.x);
        atomicAdd(&ss[2 * lane + 1], acc.y);
        atomicAdd(&ss[64 + 2 * lane], acc.x * acc.x);
        atomicAdd(&ss[64 + 2 * lane + 1], acc.y * acc.y);
    }
    __syncthreads();
    if (tid < 128) atomicAdd(&g_stats[layer * 128 + tid], ss[tid]);
}

// ---------------- gemm_dual (TF32 mma.sync): z=relu(bn(t)); H=relu(z@W2+b2);
//                  y_next = H@W1n (bf16 out); pool H ----------------
// block = 128 nodes, 8 warps; warp = 16-row m-tile x 64 cols (8 n-tiles), K=64 (8 k-steps)
__global__ void __launch_bounds__(256) gemm_dual_kernel(
    const float* __restrict__ W2, const float* __restrict__ B2,
    const int* __restrict__ batch, int pool_off,
    const float* __restrict__ W1n, int has_next, int N,
    int layer, const float* __restrict__ gg, const float* __restrict__ be, float ninv)
{
    __shared__ float sA[128 * 68];    // A (z, tf32 bits) -> reused for H (f32)
    __shared__ float sB2[64 * 68];    // W2^T [n][k], tf32 bits
    __shared__ float sB1[64 * 68];    // W1n^T [n][k], tf32 bits
    __shared__ float scs[64], shs[64], b2s[64];
    int tid = threadIdx.x, wid = tid >> 5, lid = tid & 31;
    int gi = lid >> 2, ti = lid & 3;

    if (tid < 64) {
        float mean = g_stats[layer * 128 + tid] * ninv;
        float var  = g_stats[layer * 128 + 64 + tid] * ninv - mean * mean;
        float s = gg[tid] * rsqrtf(var + 1e-5f);
        scs[tid] = s;
        shs[tid] = fmaf(-mean, s, be[tid]);
        b2s[tid] = B2[tid];
    }
    __syncthreads();

    // stage A = tf32(relu(bn(g_t))): [row][k], stride 68
    int base = blockIdx.x * 128;
    #pragma unroll 2
    for (int i = tid; i < 2048; i += 256) {
        int row = i >> 4, u = i & 15;
        float4 v = make_float4(0.f, 0.f, 0.f, 0.f);
        int r = base + row;
        if (r < N) {
            float4 t = ((const float4*)g_t)[r * 16 + u];
            int cb = u * 4;
            v.x = fmaxf(fmaf(t.x, scs[cb + 0], shs[cb + 0]), 0.f);
            v.y = fmaxf(fmaf(t.y, scs[cb + 1], shs[cb + 1]), 0.f);
            v.z = fmaxf(fmaf(t.z, scs[cb + 2], shs[cb + 2]), 0.f);
            v.w = fmaxf(fmaf(t.w, scs[cb + 3], shs[cb + 3]), 0.f);
        }
        float* ap = &sA[row * 68 + u * 4];
        ap[0] = __uint_as_float(tf32_cvt(v.x));
        ap[1] = __uint_as_float(tf32_cvt(v.y));
        ap[2] = __uint_as_float(tf32_cvt(v.z));
        ap[3] = __uint_as_float(tf32_cvt(v.w));
    }
    // stage B2/B1 transposed: W[k][n] -> sB[n][k]
    #pragma unroll 2
    for (int i = tid; i < 4096; i += 256) {
        int k = i >> 6, n = i & 63;
        sB2[n * 68 + k] = __uint_as_float(tf32_cvt(W2[i]));
    }
    if (has_next) {
        #pragma unroll 2
        for (int i = tid; i < 4096; i += 256) {
            int k = i >> 6, n = i & 63;
            sB1[n * 68 + k] = __uint_as_float(tf32_cvt(W1n[i]));
        }
    }
    __syncthreads();

    // MMA1: D = A @ W2^T, bias pre-loaded into accumulators
    int arow = wid * 16 + gi;                 // rows arow (a0/a2) and arow+8 (a1/a3)
    float d[8][4];
    #pragma unroll
    for (int j = 0; j < 8; j++) {
        float bb0 = b2s[8 * j + 2 * ti], bb1 = b2s[8 * j + 2 * ti + 1];
        d[j][0] = bb0; d[j][1] = bb1; d[j][2] = bb0; d[j][3] = bb1;
    }
    #pragma unroll
    for (int t = 0; t < 8; t++) {
        int kb = t * 8;
        unsigned a0 = __float_as_uint(sA[arow * 68 + kb + ti]);
        unsigned a1 = __float_as_uint(sA[(arow + 8) * 68 + kb + ti]);
        unsigned a2 = __float_as_uint(sA[arow * 68 + kb + ti + 4]);
        unsigned a3 = __float_as_uint(sA[(arow + 8) * 68 + kb + ti + 4]);
        #pragma unroll
        for (int j = 0; j < 8; j++) {
            unsigned b0 = __float_as_uint(sB2[(8 * j + gi) * 68 + kb + ti]);
            unsigned b1 = __float_as_uint(sB2[(8 * j + gi) * 68 + kb + ti + 4]);
            mma_tf32(d[j], a0, a1, a2, a3, b0, b1);
        }
    }

    // H = relu(D); overwrite own-warp rows of sA (A fully consumed by this warp)
    #pragma unroll
    for (int j = 0; j < 8; j++) {
        float h0 = fmaxf(d[j][0], 0.f), h1 = fmaxf(d[j][1], 0.f);
        float h2 = fmaxf(d[j][2], 0.f), h3 = fmaxf(d[j][3], 0.f);
        *(float2*)&sA[arow * 68 + 8 * j + 2 * ti]       = make_float2(h0, h1);
        *(float2*)&sA[(arow + 8) * 68 + 8 * j + 2 * ti] = make_float2(h2, h3);
    }
    __syncwarp();

    // MMA2: y_next = H @ W1n^T (tf32), write bf16
    if (has_next) {
        float e[8][4];
        #pragma unroll
        for (int j = 0; j < 8; j++) { e[j][0] = 0.f; e[j][1] = 0.f; e[j][2] = 0.f; e[j][3] = 0.f; }
        #pragma unroll
        for (int t = 0; t < 8; t++) {
            int kb = t * 8;
            unsigned a0 = tf32_cvt(sA[arow * 68 + kb + ti]);
            unsigned a1 = tf32_cvt(sA[(arow + 8) * 68 + kb + ti]);
            unsigned a2 = tf32_cvt(sA[arow * 68 + kb + ti + 4]);
            unsigned a3 = tf32_cvt(sA[(arow + 8) * 68 + kb + ti + 4]);
            #pragma unroll
            for (int j = 0; j < 8; j++) {
                unsigned b0 = __float_as_uint(sB1[(8 * j + gi) * 68 + kb + ti]);
                unsigned b1 = __float_as_uint(sB1[(8 * j + gi) * 68 + kb + ti + 4]);
                mma_tf32(e[j], a0, a1, a2, a3, b0, b1);
            }
        }
        int r0 = base + arow, r1 = base + arow + 8;
        if (r0 < N) {
            #pragma unroll
            for (int j = 0; j < 8; j++)
                g_yb[r0 * 32 + 4 * j + ti] = __floats2bfloat162_rn(e[j][0], e[j][1]);
        }
        if (r1 < N) {
            #pragma unroll
            for (int j = 0; j < 8; j++)
                g_yb[r1 * 32 + 4 * j + ti] = __floats2bfloat162_rn(e[j][2], e[j][3]);
        }
    }

    // pooling from sA H (f32), run-compressed (batch sorted): warp rows wid*16..+15, lane = cpair
    {
        int prow = wid * 16;
        int cp = lid;
        int bprev = -1; float p0 = 0.f, p1 = 0.f;
        #pragma unroll
        for (int j = 0; j < 16; j++) {
            int rr = base + prow + j;
            if (rr < N) {
                float2 hv = *(const float2*)&sA[(prow + j) * 68 + 2 * cp];
                int bg = batch[rr];
                if (bg != bprev) {
                    if (bprev >= 0)
                        atomicAdd((float2*)&g_pooled[bprev * 256 + pool_off + 2 * cp],
                                  make_float2(p0, p1));
                    bprev = bg; p0 = 0.f; p1 = 0.f;
                }
                p0 += hv.x; p1 += hv.y;
            }
        }
        if (bprev >= 0)
            atomicAdd((float2*)&g_pooled[bprev * 256 + pool_off + 2 * cp],
                      make_float2(p0, p1));
    }
}

// ---------------- head ----------------
__global__ void head1_kernel(const float* __restrict__ W, const float* __restrict__ B)
{
    int gph = blockIdx.x, c = threadIdx.x;   // <<<512,64>>>
    __shared__ float xs[256];
    #pragma unroll
    for (int i = c; i < 256; i += 64) xs[i] = g_pooled[gph * 256 + i];
    __syncthreads();
    float a = B[c];
    #pragma unroll 4
    for (int k = 0; k < 256; k++) a = fmaf(xs[k], __ldg(&W[k * 64 + c]), a);
    g_head1[gph * 64 + c] = a;
}

__global__ void head_bn_kernel(const float* __restrict__ g, const float* __restrict__ be)
{
    int c = blockIdx.x; int t = threadIdx.x;  // <<<64,256>>>
    __shared__ float red[256];
    float v0 = g_head1[t * 64 + c];
    float v1 = g_head1[(t + 256) * 64 + c];
    red[t] = v0 + v1;
    __syncthreads();
    for (int o = 128; o > 0; o >>= 1) { if (t < o) red[t] += red[t + o]; __syncthreads(); }
    float mean = red[0] * (1.0f / 512.0f);
    __syncthreads();
    float d0 = v0 - mean, d1 = v1 - mean;
    red[t] = d0 * d0 + d1 * d1;
    __syncthreads();
    for (int o = 128; o > 0; o >>= 1) { if (t < o) red[t] += red[t + o]; __syncthreads(); }
    if (t == 0) {
        float var = red[0] * (1.0f / 512.0f);
        float s = g[c] * rsqrtf(var + 1e-5f);
        g_scale[c] = s;
        g_shift[c] = fmaf(-mean, s, be[c]);
    }
}

__global__ void head_final_kernel(const float* __restrict__ W, const float* __restrict__ B,
                                  float* __restrict__ out)
{
    int gph = blockIdx.x; int c = threadIdx.x;   // <<<512,64>>>
    __shared__ float hn[64];
    __shared__ float logits[10];
    hn[c] = fmaxf(fmaf(g_head1[gph * 64 + c], g_scale[c], g_shift[c]), 0.f);
    __syncthreads();
    if (c < 10) {
        float a = B[c];
        #pragma unroll
        for (int k = 0; k < 64; k++) a = fmaf(hn[k], W[k * 10 + c], a);
        logits[c] = a;
    }
    __syncthreads();
    if (c == 0) {
        float m = logits[0];
        #pragma unroll
        for (int j = 1; j < 10; j++) m = fmaxf(m, logits[j]);
        float ssum = 0.f;
        #pragma unroll
        for (int j = 0; j < 10; j++) ssum += expf(logits[j] - m);
        float lse = m + logf(ssum);
        #pragma unroll
        for (int j = 0; j < 10; j++) out[gph * 10 + j] = logits[j] - lse;
    }
}

// ---------------- launch ----------------
extern "C" void kernel_launch(void* const* d_in, const int* in_sizes, int n_in,
                              void* d_out, int out_size)
{
    const float* x     = (const float*)d_in[0];
    const int*   ei    = (const int*)d_in[1];
    const int*   batch = (const int*)d_in[2];
    const float* eps   = (const float*)d_in[3];

    zero_all_kernel<<<(ZW + 255) / 256, 256>>>();                 // 1
    hist_kernel<<<(NE + 255) / 256, 256>>>(ei);                   // 2
    scan1_kernel<<<NSB, 1024>>>();                                // 3
    gemm_pre_kernel<<<(NN + 63) / 64, 128>>>(x, (const float*)d_in[4], NN);  // 4 (profiled)
    scan2_kernel<<<1, 128>>>();                                   // 5
    scan3_kernel<<<NSB, 1024>>>();                                // 6
    csr_scatter_kernel<<<(NE + 255) / 256, 256>>>(ei);            // 7

    for (int l = 0; l < 4; l++) {
        const float *b1, *gg, *be, *W2, *b2;
        if (l == 0) {
            b1 = (const float*)d_in[5];
            gg = (const float*)d_in[6]; be = (const float*)d_in[7];
            W2 = (const float*)d_in[8]; b2 = (const float*)d_in[9];
        } else {
            int j = l - 1;
            b1 = (const float*)d_in[11] + j * 64;
            gg = (const float*)d_in[12] + j * 64; be = (const float*)d_in[13] + j * 64;
            W2 = (const float*)d_in[14] + j * 64 * 64; b2 = (const float*)d_in[15] + j * 64;
        }
        const float* W1n = (l < 3) ? ((const float*)d_in[10] + l * 64 * 64) : (const float*)d_in[10];
        int has_next = (l < 3) ? 1 : 0;

        aggregate_kernel<<<(NN * 32 + 255) / 256, 256>>>(eps, l, b1);
        gemm_dual_kernel<<<(NN + 127) / 128, 256>>>(W2, b2, batch, l * 64, W1n, has_next, NN,
                                                    l, gg, be, 1.0f / (float)NN);
    }

    head1_kernel<<<NG, 64>>>((const float*)d_in[16], (const float*)d_in[17]);
    head_bn_kernel<<<64, 256>>>((const float*)d_in[18], (const float*)d_in[19]);
    head_final_kernel<<<NG, 64>>>((const float*)d_in[20], (const float*)d_in[21], (float*)d_out);
}

// round 12
// speedup vs baseline: 2.0311x; 1.0128x over previous
#include <cuda_runtime.h>
#include <cuda_bf16.h>
#include <math.h>

#define NN 100000
#define NE 1600000
#define NG 512
#define NSB 98   // scan blocks of 1024 -> covers 100352 >= NN

// ---------------- device scratch ----------------
__device__ __align__(256) __nv_bfloat162 g_yb[NN * 32];  // y in bf16x2: 128B/node
__device__ __align__(256) float g_t[NN * 64];
__device__ float g_stats[4 * 128];
__device__ float g_scale[64];
__device__ float g_shift[64];
__device__ float g_pooled[NG * 256];
__device__ float g_head1[NG * 64];
__device__ int   g_deg[NN];
__device__ int   g_off[NN + 1];
__device__ int   g_cursor[NN];
__device__ int   g_srcs[NE];
__device__ int   g_bsum[NSB];
__device__ int   g_boff[NSB];

// ---------------- tf32 mma helpers ----------------
__device__ __forceinline__ unsigned tf32_cvt(float x) {
    unsigned r;
    asm("cvt.rna.tf32.f32 %0, %1;" : "=r"(r) : "f"(x));
    return r;
}
__device__ __forceinline__ void mma_tf32(float* d,
                                         unsigned a0, unsigned a1, unsigned a2, unsigned a3,
                                         unsigned b0, unsigned b1) {
    asm("mma.sync.aligned.m16n8k8.row.col.f32.tf32.tf32.f32 "
        "{%0,%1,%2,%3}, {%4,%5,%6,%7}, {%8,%9}, {%0,%1,%2,%3};"
        : "+f"(d[0]), "+f"(d[1]), "+f"(d[2]), "+f"(d[3])
        : "r"(a0), "r"(a1), "r"(a2), "r"(a3), "r"(b0), "r"(b1));
}
__device__ __forceinline__ float4 tf32_cvt4(float4 v) {
    float4 t;
    t.x = __uint_as_float(tf32_cvt(v.x));
    t.y = __uint_as_float(tf32_cvt(v.y));
    t.z = __uint_as_float(tf32_cvt(v.z));
    t.w = __uint_as_float(tf32_cvt(v.w));
    return t;
}

// ---------------- fused zero kernel ----------------
#define ZW (131072 + 512 + NN)
__global__ void zero_all_kernel() {
    int i = blockIdx.x * 256 + threadIdx.x;
    if (i < 131072) g_pooled[i] = 0.f;
    else if (i < 131072 + 512) g_stats[i - 131072] = 0.f;
    else if (i < ZW) g_deg[i - 131072 - 512] = 0;
}

// ---------------- CSR build ----------------
__global__ void hist_kernel(const int* __restrict__ ei) {
    int e = blockIdx.x * 256 + threadIdx.x;
    if (e < NE) atomicAdd(&g_deg[ei[NE + e]], 1);
}
__global__ void scan1_kernel() {                  // <<<NSB,1024>>>
    __shared__ int wsum[32];
    int tid = threadIdx.x;
    int i = blockIdx.x * 1024 + tid;
    int v = (i < NN) ? g_deg[i] : 0;
    int x = v;
    #pragma unroll
    for (int o = 1; o < 32; o <<= 1) {
        int t = __shfl_up_sync(0xffffffffu, x, o);
        if ((tid & 31) >= o) x += t;
    }
    if ((tid & 31) == 31) wsum[tid >> 5] = x;
    __syncthreads();
    if (tid < 32) {
        int y = wsum[tid];
        #pragma unroll
        for (int o = 1; o < 32; o <<= 1) {
            int t = __shfl_up_sync(0xffffffffu, y, o);
            if (tid >= o) y += t;
        }
        wsum[tid] = y;
    }
    __syncthreads();
    int base = (tid >= 32) ? wsum[(tid >> 5) - 1] : 0;
    int incl = x + base;
    if (i < NN) g_off[i] = incl - v;
    if (tid == 1023) g_bsum[blockIdx.x] = incl;
}
__global__ void scan2_kernel() {                  // <<<1,128>>>
    __shared__ int s[128];
    int tid = threadIdx.x;
    int v = (tid < NSB) ? g_bsum[tid] : 0;
    s[tid] = v; __syncthreads();
    for (int off = 1; off < 128; off <<= 1) {
        int t = (tid >= off) ? s[tid - off] : 0;
        __syncthreads();
        s[tid] += t;
        __syncthreads();
    }
    if (tid < NSB) g_boff[tid] = s[tid] - v;
}
__global__ void scan3_kernel() {                  // <<<NSB,1024>>>
    int i = blockIdx.x * 1024 + threadIdx.x;
    if (i < NN) {
        int v = g_off[i] + g_boff[blockIdx.x];
        g_off[i] = v;
        g_cursor[i] = v;
    }
    if (i == 0) g_off[NN] = NE;
}
__global__ void csr_scatter_kernel(const int* __restrict__ ei) {
    int e = blockIdx.x * 256 + threadIdx.x;
    if (e < NE) {
        int s = ei[e];
        int d = ei[NE + e];
        int p = atomicAdd(&g_cursor[d], 1);
        g_srcs[p] = s;
    }
}

// ---------------- gemm_pre (TF32 mma.sync, 8 warps M/N-split): y = X @ W1_0, bf16 store ----
// block = 64 nodes, 256 thr. warp w: rows (w&3)*16 (m16 tile), cols (w>>2)*32 (4 n-tiles), K=128
__global__ void __launch_bounds__(256) gemm_pre_kernel(
    const float* __restrict__ X, const float* __restrict__ W, int N)
{
    __shared__ float sX[64 * 132];    // tf32 bits [row][k], stride 132
    __shared__ float sW[128 * 68];    // W [k][n] direct, tf32 bits, stride 68
    int tid = threadIdx.x, wid = tid >> 5, lid = tid & 31;
    int gi = lid >> 2, ti = lid & 3;
    int base = blockIdx.x * 64;

    // stage X (tf32), float4, conflict-free
    const float4* Xv = (const float4*)X;
    #pragma unroll 4
    for (int i = tid; i < 2048; i += 256) {
        int row = i >> 5, q = i & 31;
        float4 v = make_float4(0.f, 0.f, 0.f, 0.f);
        int r = base + row;
        if (r < N) v = Xv[r * 32 + q];
        *(float4*)&sX[row * 132 + q * 4] = tf32_cvt4(v);
    }
    // stage W [k][n] directly (no transpose), float4 coalesced
    const float4* Wv = (const float4*)W;
    #pragma unroll 4
    for (int i = tid; i < 2048; i += 256) {
        int k = i >> 4, q = i & 15;
        *(float4*)&sW[k * 68 + q * 4] = tf32_cvt4(Wv[i]);
    }
    __syncthreads();

    int arow = (wid & 3) * 16 + gi;
    int ng = (wid >> 2) * 32;           // column group base
    float e[4][4];
    #pragma unroll
    for (int j = 0; j < 4; j++) { e[j][0] = 0.f; e[j][1] = 0.f; e[j][2] = 0.f; e[j][3] = 0.f; }
    #pragma unroll
    for (int t = 0; t < 16; t++) {
        int kb = t * 8;
        unsigned a0 = __float_as_uint(sX[arow * 132 + kb + ti]);
        unsigned a1 = __float_as_uint(sX[(arow + 8) * 132 + kb + ti]);
        unsigned a2 = __float_as_uint(sX[arow * 132 + kb + ti + 4]);
        unsigned a3 = __float_as_uint(sX[(arow + 8) * 132 + kb + ti + 4]);
        #pragma unroll
        for (int j = 0; j < 4; j++) {
            unsigned b0 = __float_as_uint(sW[(kb + ti) * 68 + ng + 8 * j + gi]);
            unsigned b1 = __float_as_uint(sW[(kb + ti + 4) * 68 + ng + 8 * j + gi]);
            mma_tf32(e[j], a0, a1, a2, a3, b0, b1);
        }
    }
    // write y bf16x2: rows arow/arow+8, cpair = ng/2 + 4j + ti
    int r0 = base + arow, r1 = base + arow + 8;
    int cpb = ng >> 1;
    if (r0 < N) {
        #pragma unroll
        for (int j = 0; j < 4; j++)
            g_yb[r0 * 32 + cpb + 4 * j + ti] = __floats2bfloat162_rn(e[j][0], e[j][1]);
    }
    if (r1 < N) {
        #pragma unroll
        for (int j = 0; j < 4; j++)
            g_yb[r1 * 32 + cpb + 4 * j + ti] = __floats2bfloat162_rn(e[j][2], e[j][3]);
    }
}

// ---------------- aggregate: warp/node, t = (1+eps)y + gather(y) + b1; BN stats ----------------
__global__ void __launch_bounds__(256) aggregate_kernel(
    const float* __restrict__ eps_arr, int layer, const float* __restrict__ b1)
{
    __shared__ float ss[128];
    int tid = threadIdx.x;
    if (tid < 128) ss[tid] = 0.f;
    __syncthreads();

    int warp = (blockIdx.x * 256 + tid) >> 5;
    int lane = tid & 31;
    if (warp < NN) {
        float oe = 1.0f + __ldg(&eps_arr[layer]);
        int beg = g_off[warp], end = g_off[warp + 1];
        float2 self = __bfloat1622float2(g_yb[warp * 32 + lane]);
        float2 acc = make_float2(self.x * oe, self.y * oe);
        for (int bse = beg; bse < end; bse += 32) {
            int m = end - bse; if (m > 32) m = 32;
            int idx = (lane < m) ? g_srcs[bse + lane] : 0;
            int t = 0;
            for (; t + 4 <= m; t += 4) {
                int s0 = __shfl_sync(0xffffffffu, idx, t);
                int s1 = __shfl_sync(0xffffffffu, idx, t + 1);
                int s2 = __shfl_sync(0xffffffffu, idx, t + 2);
                int s3 = __shfl_sync(0xffffffffu, idx, t + 3);
                float2 a = __bfloat1622float2(g_yb[s0 * 32 + lane]);
                float2 b = __bfloat1622float2(g_yb[s1 * 32 + lane]);
                float2 cc = __bfloat1622float2(g_yb[s2 * 32 + lane]);
                float2 d = __bfloat1622float2(g_yb[s3 * 32 + lane]);
                acc.x += (a.x + b.x) + (cc.x + d.x);
                acc.y += (a.y + b.y) + (cc.y + d.y);
            }
            for (; t < m; t++) {
                int s0 = __shfl_sync(0xffffffffu, idx, t);
                float2 a = __bfloat1622float2(g_yb[s0 * 32 + lane]);
                acc.x += a.x; acc.y += a.y;
            }
        }
        float2 bb = *(const float2*)&b1[2 * lane];
        acc.x += bb.x; acc.y += bb.y;
        *(float2*)&g_t[warp * 64 + 2 * lane] = acc;
        atomicAdd(&ss[2 * lane], acc.x);
        atomicAdd(&ss[2 * lane + 1], acc.y);
        atomicAdd(&ss[64 + 2 * lane], acc.x * acc.x);
        atomicAdd(&ss[64 + 2 * lane + 1], acc.y * acc.y);
    }
    __syncthreads();
    if (tid < 128) atomicAdd(&g_stats[layer * 128 + tid], ss[tid]);
}

// ---------------- gemm_dual (TF32 mma.sync): z=relu(bn(t)); H=relu(z@W2+b2);
//                  y_next = H@W1n (bf16 out); pool H ----------------
// block = 128 nodes, 8 warps; warp = 16-row m-tile x 64 cols (8 n-tiles), K=64 (8 k-steps)
__global__ void __launch_bounds__(256) gemm_dual_kernel(
    const float* __restrict__ W2, const float* __restrict__ B2,
    const int* __restrict__ batch, int pool_off,
    const float* __restrict__ W1n, int has_next, int N,
    int layer, const float* __restrict__ gg, const float* __restrict__ be, float ninv)
{
    __shared__ float sA[128 * 68];    // A (z, tf32 bits) -> reused for H (f32)
    __shared__ float sB2[64 * 68];    // W2 [k][n] direct, tf32 bits
    __shared__ float sB1[64 * 68];    // W1n [k][n] direct, tf32 bits
    __shared__ float scs[64], shs[64], b2s[64];
    int tid = threadIdx.x, wid = tid >> 5, lid = tid & 31;
    int gi = lid >> 2, ti = lid & 3;

    if (tid < 64) {
        float mean = g_stats[layer * 128 + tid] * ninv;
        float var  = g_stats[layer * 128 + 64 + tid] * ninv - mean * mean;
        float s = gg[tid] * rsqrtf(var + 1e-5f);
        scs[tid] = s;
        shs[tid] = fmaf(-mean, s, be[tid]);
        b2s[tid] = B2[tid];
    }
    __syncthreads();

    // stage A = tf32(relu(bn(g_t))): [row][k], stride 68
    int base = blockIdx.x * 128;
    #pragma unroll 2
    for (int i = tid; i < 2048; i += 256) {
        int row = i >> 4, u = i & 15;
        float4 v = make_float4(0.f, 0.f, 0.f, 0.f);
        int r = base + row;
        if (r < N) {
            float4 t = ((const float4*)g_t)[r * 16 + u];
            int cb = u * 4;
            v.x = fmaxf(fmaf(t.x, scs[cb + 0], shs[cb + 0]), 0.f);
            v.y = fmaxf(fmaf(t.y, scs[cb + 1], shs[cb + 1]), 0.f);
            v.z = fmaxf(fmaf(t.z, scs[cb + 2], shs[cb + 2]), 0.f);
            v.w = fmaxf(fmaf(t.w, scs[cb + 3], shs[cb + 3]), 0.f);
        }
        *(float4*)&sA[row * 68 + u * 4] = tf32_cvt4(v);
    }
    // stage B2/B1 direct [k][n], float4 coalesced
    {
        const float4* Wv = (const float4*)W2;
        #pragma unroll 2
        for (int i = tid; i < 1024; i += 256) {
            int k = i >> 4, q = i & 15;
            *(float4*)&sB2[k * 68 + q * 4] = tf32_cvt4(Wv[i]);
        }
    }
    if (has_next) {
        const float4* Wv = (const float4*)W1n;
        #pragma unroll 2
        for (int i = tid; i < 1024; i += 256) {
            int k = i >> 4, q = i & 15;
            *(float4*)&sB1[k * 68 + q * 4] = tf32_cvt4(Wv[i]);
        }
    }
    __syncthreads();

    // MMA1: D = A @ W2 (B-frag from [k][n] layout), bias pre-loaded
    int arow = wid * 16 + gi;
    float d[8][4];
    #pragma unroll
    for (int j = 0; j < 8; j++) {
        float bb0 = b2s[8 * j + 2 * ti], bb1 = b2s[8 * j + 2 * ti + 1];
        d[j][0] = bb0; d[j][1] = bb1; d[j][2] = bb0; d[j][3] = bb1;
    }
    #pragma unroll
    for (int t = 0; t < 8; t++) {
        int kb = t * 8;
        unsigned a0 = __float_as_uint(sA[arow * 68 + kb + ti]);
        unsigned a1 = __float_as_uint(sA[(arow + 8) * 68 + kb + ti]);
        unsigned a2 = __float_as_uint(sA[arow * 68 + kb + ti + 4]);
        unsigned a3 = __float_as_uint(sA[(arow + 8) * 68 + kb + ti + 4]);
        #pragma unroll
        for (int j = 0; j < 8; j++) {
            unsigned b0 = __float_as_uint(sB2[(kb + ti) * 68 + 8 * j + gi]);
            unsigned b1 = __float_as_uint(sB2[(kb + ti + 4) * 68 + 8 * j + gi]);
            mma_tf32(d[j], a0, a1, a2, a3, b0, b1);
        }
    }

    // H = relu(D); overwrite own-warp rows of sA
    #pragma unroll
    for (int j = 0; j < 8; j++) {
        float h0 = fmaxf(d[j][0], 0.f), h1 = fmaxf(d[j][1], 0.f);
        float h2 = fmaxf(d[j][2], 0.f), h3 = fmaxf(d[j][3], 0.f);
        *(float2*)&sA[arow * 68 + 8 * j + 2 * ti]       = make_float2(h0, h1);
        *(float2*)&sA[(arow + 8) * 68 + 8 * j + 2 * ti] = make_float2(h2, h3);
    }
    __syncwarp();

    // MMA2: y_next = H @ W1n, write bf16
    if (has_next) {
        float e[8][4];
        #pragma unroll
        for (int j = 0; j < 8; j++) { e[j][0] = 0.f; e[j][1] = 0.f; e[j][2] = 0.f; e[j][3] = 0.f; }
        #pragma unroll
        for (int t = 0; t < 8; t++) {
            int kb = t * 8;
            unsigned a0 = tf32_cvt(sA[arow * 68 + kb + ti]);
            unsigned a1 = tf32_cvt(sA[(arow + 8) * 68 + kb + ti]);
            unsigned a2 = tf32_cvt(sA[arow * 68 + kb + ti + 4]);
            unsigned a3 = tf32_cvt(sA[(arow + 8) * 68 + kb + ti + 4]);
            #pragma unroll
            for (int j = 0; j < 8; j++) {
                unsigned b0 = __float_as_uint(sB1[(kb + ti) * 68 + 8 * j + gi]);
                unsigned b1 = __float_as_uint(sB1[(kb + ti + 4) * 68 + 8 * j + gi]);
                mma_tf32(e[j], a0, a1, a2, a3, b0, b1);
            }
        }
        int r0 = base + arow, r1 = base + arow + 8;
        if (r0 < N) {
            #pragma unroll
            for (int j = 0; j < 8; j++)
                g_yb[r0 * 32 + 4 * j + ti] = __floats2bfloat162_rn(e[j][0], e[j][1]);
        }
        if (r1 < N) {
            #pragma unroll
            for (int j = 0; j < 8; j++)
                g_yb[r1 * 32 + 4 * j + ti] = __floats2bfloat162_rn(e[j][2], e[j][3]);
        }
    }

    // pooling from sA H (f32), run-compressed (batch sorted): warp rows wid*16..+15, lane = cpair
    {
        int prow = wid * 16;
        int cp = lid;
        int bprev = -1; float p0 = 0.f, p1 = 0.f;
        #pragma unroll
        for (int j = 0; j < 16; j++) {
            int rr = base + prow + j;
            if (rr < N) {
                float2 hv = *(const float2*)&sA[(prow + j) * 68 + 2 * cp];
                int bg = batch[rr];
                if (bg != bprev) {
                    if (bprev >= 0)
                        atomicAdd((float2*)&g_pooled[bprev * 256 + pool_off + 2 * cp],
                                  make_float2(p0, p1));
                    bprev = bg; p0 = 0.f; p1 = 0.f;
                }
                p0 += hv.x; p1 += hv.y;
            }
        }
        if (bprev >= 0)
            atomicAdd((float2*)&g_pooled[bprev * 256 + pool_off + 2 * cp],
                      make_float2(p0, p1));
    }
}

// ---------------- head ----------------
__global__ void head1_kernel(const float* __restrict__ W, const float* __restrict__ B)
{
    int gph = blockIdx.x, c = threadIdx.x;   // <<<512,64>>>
    __shared__ float xs[256];
    #pragma unroll
    for (int i = c; i < 256; i += 64) xs[i] = g_pooled[gph * 256 + i];
    __syncthreads();
    float a = B[c];
    #pragma unroll 4
    for (int k = 0; k < 256; k++) a = fmaf(xs[k], __ldg(&W[k * 64 + c]), a);
    g_head1[gph * 64 + c] = a;
}

__global__ void head_bn_kernel(const float* __restrict__ g, const float* __restrict__ be)
{
    int c = blockIdx.x; int t = threadIdx.x;  // <<<64,256>>>
    __shared__ float red[256];
    float v0 = g_head1[t * 64 + c];
    float v1 = g_head1[(t + 256) * 64 + c];
    red[t] = v0 + v1;
    __syncthreads();
    for (int o = 128; o > 0; o >>= 1) { if (t < o) red[t] += red[t + o]; __syncthreads(); }
    float mean = red[0] * (1.0f / 512.0f);
    __syncthreads();
    float d0 = v0 - mean, d1 = v1 - mean;
    red[t] = d0 * d0 + d1 * d1;
    __syncthreads();
    for (int o = 128; o > 0; o >>= 1) { if (t < o) red[t] += red[t + o]; __syncthreads(); }
    if (t == 0) {
        float var = red[0] * (1.0f / 512.0f);
        float s = g[c] * rsqrtf(var + 1e-5f);
        g_scale[c] = s;
        g_shift[c] = fmaf(-mean, s, be[c]);
    }
}

__global__ void head_final_kernel(const float* __restrict__ W, const float* __restrict__ B,
                                  float* __restrict__ out)
{
    int gph = blockIdx.x; int c = threadIdx.x;   // <<<512,64>>>
    __shared__ float hn[64];
    __shared__ float logits[10];
    hn[c] = fmaxf(fmaf(g_head1[gph * 64 + c], g_scale[c], g_shift[c]), 0.f);
    __syncthreads();
    if (c < 10) {
        float a = B[c];
        #pragma unroll
        for (int k = 0; k < 64; k++) a = fmaf(hn[k], W[k * 10 + c], a);
        logits[c] = a;
    }
    __syncthreads();
    if (c == 0) {
        float m = logits[0];
        #pragma unroll
        for (int j = 1; j < 10; j++) m = fmaxf(m, logits[j]);
        float ssum = 0.f;
        #pragma unroll
        for (int j = 0; j < 10; j++) ssum += expf(logits[j] - m);
        float lse = m + logf(ssum);
        #pragma unroll
        for (int j = 0; j < 10; j++) out[gph * 10 + j] = logits[j] - lse;
    }
}

// ---------------- launch ----------------
extern "C" void kernel_launch(void* const* d_in, const int* in_sizes, int n_in,
                              void* d_out, int out_size)
{
    const float* x     = (const float*)d_in[0];
    const int*   ei    = (const int*)d_in[1];
    const int*   batch = (const int*)d_in[2];
    const float* eps   = (const float*)d_in[3];

    zero_all_kernel<<<(ZW + 255) / 256, 256>>>();                 // 1
    hist_kernel<<<(NE + 255) / 256, 256>>>(ei);                   // 2
    scan1_kernel<<<NSB, 1024>>>();                                // 3
    gemm_pre_kernel<<<(NN + 63) / 64, 256>>>(x, (const float*)d_in[4], NN);  // 4 (profiled)
    scan2_kernel<<<1, 128>>>();                                   // 5
    scan3_kernel<<<NSB, 1024>>>();                                // 6
    csr_scatter_kernel<<<(NE + 255) / 256, 256>>>(ei);            // 7

    for (int l = 0; l < 4; l++) {
        const float *b1, *gg, *be, *W2, *b2;
        if (l == 0) {
            b1 = (const float*)d_in[5];
            gg = (const float*)d_in[6]; be = (const float*)d_in[7];
            W2 = (const float*)d_in[8]; b2 = (const float*)d_in[9];
        } else {
            int j = l - 1;
            b1 = (const float*)d_in[11] + j * 64;
            gg = (const float*)d_in[12] + j * 64; be = (const float*)d_in[13] + j * 64;
            W2 = (const float*)d_in[14] + j * 64 * 64; b2 = (const float*)d_in[15] + j * 64;
        }
        const float* W1n = (l < 3) ? ((const float*)d_in[10] + l * 64 * 64) : (const float*)d_in[10];
        int has_next = (l < 3) ? 1 : 0;

        aggregate_kernel<<<(NN * 32 + 255) / 256, 256>>>(eps, l, b1);
        gemm_dual_kernel<<<(NN + 127) / 128, 256>>>(W2, b2, batch, l * 64, W1n, has_next, NN,
                                                    l, gg, be, 1.0f / (float)NN);
    }

    head1_kernel<<<NG, 64>>>((const float*)d_in[16], (const float*)d_in[17]);
    head_bn_kernel<<<64, 256>>>((const float*)d_in[18], (const float*)d_in[19]);
    head_final_kernel<<<NG, 64>>>((const float*)d_in[20], (const float*)d_in[21], (float*)d_out);
}

// round 13
// speedup vs baseline: 2.1509x; 1.0590x over previous
#include <cuda_runtime.h>
#include <cuda_bf16.h>
#include <math.h>

#define NN 100000
#define NE 1600000
#define NG 512
#define NSB 98   // scan blocks of 1024 -> covers 100352 >= NN

// ---------------- device scratch ----------------
__device__ __align__(256) __nv_bfloat162 g_yb[NN * 32];  // y in bf16x2: 128B/node
__device__ __align__(256) float g_t[NN * 64];
__device__ float g_stats[4 * 128];
__device__ float g_scale[64];
__device__ float g_shift[64];
__device__ float g_pooled[NG * 256];
__device__ float g_head1[NG * 64];
__device__ int   g_deg[NN];
__device__ int   g_off[NN + 1];
__device__ int   g_cursor[NN];
__device__ int   g_srcs[NE];
__device__ int   g_bsum[NSB];

// ---------------- tf32 mma helpers ----------------
__device__ __forceinline__ unsigned tf32_cvt(float x) {
    unsigned r;
    asm("cvt.rna.tf32.f32 %0, %1;" : "=r"(r) : "f"(x));
    return r;
}
__device__ __forceinline__ void mma_tf32(float* d,
                                         unsigned a0, unsigned a1, unsigned a2, unsigned a3,
                                         unsigned b0, unsigned b1) {
    asm("mma.sync.aligned.m16n8k8.row.col.f32.tf32.tf32.f32 "
        "{%0,%1,%2,%3}, {%4,%5,%6,%7}, {%8,%9}, {%0,%1,%2,%3};"
        : "+f"(d[0]), "+f"(d[1]), "+f"(d[2]), "+f"(d[3])
        : "r"(a0), "r"(a1), "r"(a2), "r"(a3), "r"(b0), "r"(b1));
}
__device__ __forceinline__ float4 tf32_cvt4(float4 v) {
    float4 t;
    t.x = __uint_as_float(tf32_cvt(v.x));
    t.y = __uint_as_float(tf32_cvt(v.y));
    t.z = __uint_as_float(tf32_cvt(v.z));
    t.w = __uint_as_float(tf32_cvt(v.w));
    return t;
}

// ---------------- fused zero kernel ----------------
#define ZW (131072 + 512 + NN)
__global__ void zero_all_kernel() {
    int i = blockIdx.x * 256 + threadIdx.x;
    if (i < 131072) g_pooled[i] = 0.f;
    else if (i < 131072 + 512) g_stats[i - 131072] = 0.f;
    else if (i < ZW) g_deg[i - 131072 - 512] = 0;
}

// ---------------- CSR build ----------------
__global__ void hist_kernel(const int* __restrict__ ei) {
    int e = blockIdx.x * 256 + threadIdx.x;
    if (e < NE) atomicAdd(&g_deg[ei[NE + e]], 1);
}
__global__ void scan1_kernel() {                  // <<<NSB,1024>>>
    __shared__ int wsum[32];
    int tid = threadIdx.x;
    int i = blockIdx.x * 1024 + tid;
    int v = (i < NN) ? g_deg[i] : 0;
    int x = v;
    #pragma unroll
    for (int o = 1; o < 32; o <<= 1) {
        int t = __shfl_up_sync(0xffffffffu, x, o);
        if ((tid & 31) >= o) x += t;
    }
    if ((tid & 31) == 31) wsum[tid >> 5] = x;
    __syncthreads();
    if (tid < 32) {
        int y = wsum[tid];
        #pragma unroll
        for (int o = 1; o < 32; o <<= 1) {
            int t = __shfl_up_sync(0xffffffffu, y, o);
            if (tid >= o) y += t;
        }
        wsum[tid] = y;
    }
    __syncthreads();
    int base = (tid >= 32) ? wsum[(tid >> 5) - 1] : 0;
    int incl = x + base;
    if (i < NN) g_off[i] = incl - v;
    if (tid == 1023) g_bsum[blockIdx.x] = incl;
}
// scan3: each block redundantly scans the NSB block sums (absorbs old scan2)
__global__ void scan3_kernel() {                  // <<<NSB,1024>>>
    __shared__ int bs[128];
    int tid = threadIdx.x;
    if (tid < 128) bs[tid] = (tid < NSB) ? g_bsum[tid] : 0;
    __syncthreads();
    #pragma unroll
    for (int o = 1; o < 128; o <<= 1) {
        int t = 0;
        if (tid < 128 && tid >= o) t = bs[tid - o];
        __syncthreads();
        if (tid < 128) bs[tid] += t;
        __syncthreads();
    }
    int base = (blockIdx.x > 0) ? bs[blockIdx.x - 1] : 0;
    int i = blockIdx.x * 1024 + tid;
    if (i < NN) {
        int v = g_off[i] + base;
        g_off[i] = v;
        g_cursor[i] = v;
    }
    if (i == 0) g_off[NN] = NE;
}
__global__ void csr_scatter_kernel(const int* __restrict__ ei) {
    int e = blockIdx.x * 256 + threadIdx.x;
    if (e < NE) {
        int s = ei[e];
        int d = ei[NE + e];
        int p = atomicAdd(&g_cursor[d], 1);
        g_srcs[p] = s;
    }
}

// ---------------- gemm_pre (TF32 mma.sync, 8 warps M/N-split): y = X @ W1_0, bf16 store ----
// block = 64 nodes, 256 thr. warp w: rows (w&3)*16, cols (w>>2)*32, K=128
__global__ void __launch_bounds__(256) gemm_pre_kernel(
    const float* __restrict__ X, const float* __restrict__ W, int N)
{
    __shared__ float sX[64 * 132];    // tf32 bits [row][k], stride 132
    __shared__ float sW[128 * 72];    // W [k][n] direct, stride 72 (conflict-free B-frags)
    int tid = threadIdx.x, wid = tid >> 5, lid = tid & 31;
    int gi = lid >> 2, ti = lid & 3;
    int base = blockIdx.x * 64;

    const float4* Xv = (const float4*)X;
    #pragma unroll 4
    for (int i = tid; i < 2048; i += 256) {
        int row = i >> 5, q = i & 31;
        float4 v = make_float4(0.f, 0.f, 0.f, 0.f);
        int r = base + row;
        if (r < N) v = Xv[r * 32 + q];
        *(float4*)&sX[row * 132 + q * 4] = tf32_cvt4(v);
    }
    const float4* Wv = (const float4*)W;
    #pragma unroll 4
    for (int i = tid; i < 2048; i += 256) {
        int k = i >> 4, q = i & 15;
        *(float4*)&sW[k * 72 + q * 4] = tf32_cvt4(Wv[i]);
    }
    __syncthreads();

    int arow = (wid & 3) * 16 + gi;
    int ng = (wid >> 2) * 32;
    float e[4][4];
    #pragma unroll
    for (int j = 0; j < 4; j++) { e[j][0] = 0.f; e[j][1] = 0.f; e[j][2] = 0.f; e[j][3] = 0.f; }
    #pragma unroll
    for (int t = 0; t < 16; t++) {
        int kb = t * 8;
        unsigned a0 = __float_as_uint(sX[arow * 132 + kb + ti]);
        unsigned a1 = __float_as_uint(sX[(arow + 8) * 132 + kb + ti]);
        unsigned a2 = __float_as_uint(sX[arow * 132 + kb + ti + 4]);
        unsigned a3 = __float_as_uint(sX[(arow + 8) * 132 + kb + ti + 4]);
        #pragma unroll
        for (int j = 0; j < 4; j++) {
            unsigned b0 = __float_as_uint(sW[(kb + ti) * 72 + ng + 8 * j + gi]);
            unsigned b1 = __float_as_uint(sW[(kb + ti + 4) * 72 + ng + 8 * j + gi]);
            mma_tf32(e[j], a0, a1, a2, a3, b0, b1);
        }
    }
    int r0 = base + arow, r1 = base + arow + 8;
    int cpb = ng >> 1;
    if (r0 < N) {
        #pragma unroll
        for (int j = 0; j < 4; j++)
            g_yb[r0 * 32 + cpb + 4 * j + ti] = __floats2bfloat162_rn(e[j][0], e[j][1]);
    }
    if (r1 < N) {
        #pragma unroll
        for (int j = 0; j < 4; j++)
            g_yb[r1 * 32 + cpb + 4 * j + ti] = __floats2bfloat162_rn(e[j][2], e[j][3]);
    }
}

// ---------------- aggregate: warp/node, t = (1+eps)y + gather(y) + b1; BN stats ----------------
__global__ void __launch_bounds__(256) aggregate_kernel(
    const float* __restrict__ eps_arr, int layer, const float* __restrict__ b1)
{
    __shared__ float ss[128];
    int tid = threadIdx.x;
    if (tid < 128) ss[tid] = 0.f;
    __syncthreads();

    int warp = (blockIdx.x * 256 + tid) >> 5;
    int lane = tid & 31;
    if (warp < NN) {
        float oe = 1.0f + __ldg(&eps_arr[layer]);
        int beg = g_off[warp], end = g_off[warp + 1];
        float2 self = __bfloat1622float2(g_yb[warp * 32 + lane]);
        float2 acc = make_float2(self.x * oe, self.y * oe);
        // software pipeline: prefetch next 32-edge index block
        int idx = (beg + lane < end) ? g_srcs[beg + lane] : 0;
        for (int bse = beg; bse < end; bse += 32) {
            int m = end - bse; if (m > 32) m = 32;
            int nb = bse + 32;
            int idx_next = (nb + lane < end) ? g_srcs[nb + lane] : 0;
            int t = 0;
            for (; t + 4 <= m; t += 4) {
                int s0 = __shfl_sync(0xffffffffu, idx, t);
                int s1 = __shfl_sync(0xffffffffu, idx, t + 1);
                int s2 = __shfl_sync(0xffffffffu, idx, t + 2);
                int s3 = __shfl_sync(0xffffffffu, idx, t + 3);
                float2 a = __bfloat1622float2(g_yb[s0 * 32 + lane]);
                float2 b = __bfloat1622float2(g_yb[s1 * 32 + lane]);
                float2 cc = __bfloat1622float2(g_yb[s2 * 32 + lane]);
                float2 d = __bfloat1622float2(g_yb[s3 * 32 + lane]);
                acc.x += (a.x + b.x) + (cc.x + d.x);
                acc.y += (a.y + b.y) + (cc.y + d.y);
            }
            for (; t < m; t++) {
                int s0 = __shfl_sync(0xffffffffu, idx, t);
                float2 a = __bfloat1622float2(g_yb[s0 * 32 + lane]);
                acc.x += a.x; acc.y += a.y;
            }
            idx = idx_next;
        }
        float2 bb = *(const float2*)&b1[2 * lane];
        acc.x += bb.x; acc.y += bb.y;
        *(float2*)&g_t[warp * 64 + 2 * lane] = acc;
        atomicAdd(&ss[2 * lane], acc.x);
        atomicAdd(&ss[2 * lane + 1], acc.y);
        atomicAdd(&ss[64 + 2 * lane], acc.x * acc.x);
        atomicAdd(&ss[64 + 2 * lane + 1], acc.y * acc.y);
    }
    __syncthreads();
    if (tid < 128) atomicAdd(&g_stats[layer * 128 + tid], ss[tid]);
}

// ---------------- gemm_dual (TF32 mma.sync): z=relu(bn(t)); H=relu(z@W2+b2);
//                  y_next = H@W1n (bf16 out); pool H ----------------
// block = 128 nodes, 8 warps; warp = 16-row m-tile x 64 cols (8 n-tiles), K=64 (8 k-steps)
__global__ void __launch_bounds__(256) gemm_dual_kernel(
    const float* __restrict__ W2, const float* __restrict__ B2,
    const int* __restrict__ batch, int pool_off,
    const float* __restrict__ W1n, int has_next, int N,
    int layer, const float* __restrict__ gg, const float* __restrict__ be, float ninv)
{
    __shared__ float sA[128 * 68];    // A (z, tf32 bits) -> reused for H (f32)
    __shared__ float sB2[64 * 72];    // W2 [k][n] direct, stride 72 (conflict-free B-frags)
    __shared__ float sB1[64 * 72];    // W1n [k][n] direct
    __shared__ float scs[64], shs[64], b2s[64];
    int tid = threadIdx.x, wid = tid >> 5, lid = tid & 31;
    int gi = lid >> 2, ti = lid & 3;

    if (tid < 64) {
        float mean = g_stats[layer * 128 + tid] * ninv;
        float var  = g_stats[layer * 128 + 64 + tid] * ninv - mean * mean;
        float s = gg[tid] * rsqrtf(var + 1e-5f);
        scs[tid] = s;
        shs[tid] = fmaf(-mean, s, be[tid]);
        b2s[tid] = B2[tid];
    }
    __syncthreads();

    // stage A = tf32(relu(bn(g_t))): [row][k], stride 68
    int base = blockIdx.x * 128;
    #pragma unroll 2
    for (int i = tid; i < 2048; i += 256) {
        int row = i >> 4, u = i & 15;
        float4 v = make_float4(0.f, 0.f, 0.f, 0.f);
        int r = base + row;
        if (r < N) {
            float4 t = ((const float4*)g_t)[r * 16 + u];
            int cb = u * 4;
            v.x = fmaxf(fmaf(t.x, scs[cb + 0], shs[cb + 0]), 0.f);
            v.y = fmaxf(fmaf(t.y, scs[cb + 1], shs[cb + 1]), 0.f);
            v.z = fmaxf(fmaf(t.z, scs[cb + 2], shs[cb + 2]), 0.f);
            v.w = fmaxf(fmaf(t.w, scs[cb + 3], shs[cb + 3]), 0.f);
        }
        *(float4*)&sA[row * 68 + u * 4] = tf32_cvt4(v);
    }
    // stage B2/B1 direct [k][n], float4 coalesced
    {
        const float4* Wv = (const float4*)W2;
        #pragma unroll 2
        for (int i = tid; i < 1024; i += 256) {
            int k = i >> 4, q = i & 15;
            *(float4*)&sB2[k * 72 + q * 4] = tf32_cvt4(Wv[i]);
        }
    }
    if (has_next) {
        const float4* Wv = (const float4*)W1n;
        #pragma unroll 2
        for (int i = tid; i < 1024; i += 256) {
            int k = i >> 4, q = i & 15;
            *(float4*)&sB1[k * 72 + q * 4] = tf32_cvt4(Wv[i]);
        }
    }
    __syncthreads();

    // MMA1: D = A @ W2, bias pre-loaded
    int arow = wid * 16 + gi;
    float d[8][4];
    #pragma unroll
    for (int j = 0; j < 8; j++) {
        float bb0 = b2s[8 * j + 2 * ti], bb1 = b2s[8 * j + 2 * ti + 1];
        d[j][0] = bb0; d[j][1] = bb1; d[j][2] = bb0; d[j][3] = bb1;
    }
    #pragma unroll
    for (int t = 0; t < 8; t++) {
        int kb = t * 8;
        unsigned a0 = __float_as_uint(sA[arow * 68 + kb + ti]);
        unsigned a1 = __float_as_uint(sA[(arow + 8) * 68 + kb + ti]);
        unsigned a2 = __float_as_uint(sA[arow * 68 + kb + ti + 4]);
        unsigned a3 = __float_as_uint(sA[(arow + 8) * 68 + kb + ti + 4]);
        #pragma unroll
        for (int j = 0; j < 8; j++) {
            unsigned b0 = __float_as_uint(sB2[(kb + ti) * 72 + 8 * j + gi]);
            unsigned b1 = __float_as_uint(sB2[(kb + ti + 4) * 72 + 8 * j + gi]);
            mma_tf32(d[j], a0, a1, a2, a3, b0, b1);
        }
    }

    // H = relu(D); overwrite own-warp rows of sA
    #pragma unroll
    for (int j = 0; j < 8; j++) {
        float h0 = fmaxf(d[j][0], 0.f), h1 = fmaxf(d[j][1], 0.f);
        float h2 = fmaxf(d[j][2], 0.f), h3 = fmaxf(d[j][3], 0.f);
        *(float2*)&sA[arow * 68 + 8 * j + 2 * ti]       = make_float2(h0, h1);
        *(float2*)&sA[(arow + 8) * 68 + 8 * j + 2 * ti] = make_float2(h2, h3);
    }
    __syncwarp();

    // MMA2: y_next = H @ W1n, write bf16
    if (has_next) {
        float e[8][4];
        #pragma unroll
        for (int j = 0; j < 8; j++) { e[j][0] = 0.f; e[j][1] = 0.f; e[j][2] = 0.f; e[j][3] = 0.f; }
        #pragma unroll
        for (int t = 0; t < 8; t++) {
            int kb = t * 8;
            unsigned a0 = tf32_cvt(sA[arow * 68 + kb + ti]);
            unsigned a1 = tf32_cvt(sA[(arow + 8) * 68 + kb + ti]);
            unsigned a2 = tf32_cvt(sA[arow * 68 + kb + ti + 4]);
            unsigned a3 = tf32_cvt(sA[(arow + 8) * 68 + kb + ti + 4]);
            #pragma unroll
            for (int j = 0; j < 8; j++) {
                unsigned b0 = __float_as_uint(sB1[(kb + ti) * 72 + 8 * j + gi]);
                unsigned b1 = __float_as_uint(sB1[(kb + ti + 4) * 72 + 8 * j + gi]);
                mma_tf32(e[j], a0, a1, a2, a3, b0, b1);
            }
        }
        int r0 = base + arow, r1 = base + arow + 8;
        if (r0 < N) {
            #pragma unroll
            for (int j = 0; j < 8; j++)
                g_yb[r0 * 32 + 4 * j + ti] = __floats2bfloat162_rn(e[j][0], e[j][1]);
        }
        if (r1 < N) {
            #pragma unroll
            for (int j = 0; j < 8; j++)
                g_yb[r1 * 32 + 4 * j + ti] = __floats2bfloat162_rn(e[j][2], e[j][3]);
        }
    }

    // pooling from sA H (f32), run-compressed (batch sorted)
    {
        int prow = wid * 16;
        int cp = lid;
        int bprev = -1; float p0 = 0.f, p1 = 0.f;
        #pragma unroll
        for (int j = 0; j < 16; j++) {
            int rr = base + prow + j;
            if (rr < N) {
                float2 hv = *(const float2*)&sA[(prow + j) * 68 + 2 * cp];
                int bg = batch[rr];
                if (bg != bprev) {
                    if (bprev >= 0)
                        atomicAdd((float2*)&g_pooled[bprev * 256 + pool_off + 2 * cp],
                                  make_float2(p0, p1));
                    bprev = bg; p0 = 0.f; p1 = 0.f;
                }
                p0 += hv.x; p1 += hv.y;
            }
        }
        if (bprev >= 0)
            atomicAdd((float2*)&g_pooled[bprev * 256 + pool_off + 2 * cp],
                      make_float2(p0, p1));
    }
}

// ---------------- head ----------------
__global__ void head1_kernel(const float* __restrict__ W, const float* __restrict__ B)
{
    int gph = blockIdx.x, c = threadIdx.x;   // <<<512,64>>>
    __shared__ float xs[256];
    #pragma unroll
    for (int i = c; i < 256; i += 64) xs[i] = g_pooled[gph * 256 + i];
    __syncthreads();
    float a = B[c];
    #pragma unroll 4
    for (int k = 0; k < 256; k++) a = fmaf(xs[k], __ldg(&W[k * 64 + c]), a);
    g_head1[gph * 64 + c] = a;
}

__global__ void head_bn_kernel(const float* __restrict__ g, const float* __restrict__ be)
{
    int c = blockIdx.x; int t = threadIdx.x;  // <<<64,256>>>
    __shared__ float red[256];
    float v0 = g_head1[t * 64 + c];
    float v1 = g_head1[(t + 256) * 64 + c];
    red[t] = v0 + v1;
    __syncthreads();
    for (int o = 128; o > 0; o >>= 1) { if (t < o) red[t] += red[t + o]; __syncthreads(); }
    float mean = red[0] * (1.0f / 512.0f);
    __syncthreads();
    float d0 = v0 - mean, d1 = v1 - mean;
    red[t] = d0 * d0 + d1 * d1;
    __syncthreads();
    for (int o = 128; o > 0; o >>= 1) { if (t < o) red[t] += red[t + o]; __syncthreads(); }
    if (t == 0) {
        float var = red[0] * (1.0f / 512.0f);
        float s = g[c] * rsqrtf(var + 1e-5f);
        g_scale[c] = s;
        g_shift[c] = fmaf(-mean, s, be[c]);
    }
}

__global__ void head_final_kernel(const float* __restrict__ W, const float* __restrict__ B,
                                  float* __restrict__ out)
{
    int gph = blockIdx.x; int c = threadIdx.x;   // <<<512,64>>>
    __shared__ float hn[64];
    __shared__ float logits[10];
    hn[c] = fmaxf(fmaf(g_head1[gph * 64 + c], g_scale[c], g_shift[c]), 0.f);
    __syncthreads();
    if (c < 10) {
        float a = B[c];
        #pragma unroll
        for (int k = 0; k < 64; k++) a = fmaf(hn[k], W[k * 10 + c], a);
        logits[c] = a;
    }
    __syncthreads();
    if (c == 0) {
        float m = logits[0];
        #pragma unroll
        for (int j = 1; j < 10; j++) m = fmaxf(m, logits[j]);
        float ssum = 0.f;
        #pragma unroll
        for (int j = 0; j < 10; j++) ssum += expf(logits[j] - m);
        float lse = m + logf(ssum);
        #pragma unroll
        for (int j = 0; j < 10; j++) out[gph * 10 + j] = logits[j] - lse;
    }
}

// ---------------- launch ----------------
extern "C" void kernel_launch(void* const* d_in, const int* in_sizes, int n_in,
                              void* d_out, int out_size)
{
    const float* x     = (const float*)d_in[0];
    const int*   ei    = (const int*)d_in[1];
    const int*   batch = (const int*)d_in[2];
    const float* eps   = (const float*)d_in[3];

    zero_all_kernel<<<(ZW + 255) / 256, 256>>>();                 // 1
    hist_kernel<<<(NE + 255) / 256, 256>>>(ei);                   // 2
    scan1_kernel<<<NSB, 1024>>>();                                // 3
    gemm_pre_kernel<<<(NN + 63) / 64, 256>>>(x, (const float*)d_in[4], NN);  // 4 (profiled)
    scan3_kernel<<<NSB, 1024>>>();                                // 5 (absorbs scan2)
    csr_scatter_kernel<<<(NE + 255) / 256, 256>>>(ei);            // 6

    for (int l = 0; l < 4; l++) {
        const float *b1, *gg, *be, *W2, *b2;
        if (l == 0) {
            b1 = (const float*)d_in[5];
            gg = (const float*)d_in[6]; be = (const float*)d_in[7];
            W2 = (const float*)d_in[8]; b2 = (const float*)d_in[9];
        } else {
            int j = l - 1;
            b1 = (const float*)d_in[11] + j * 64;
            gg = (const float*)d_in[12] + j * 64; be = (const float*)d_in[13] + j * 64;
            W2 = (const float*)d_in[14] + j * 64 * 64; b2 = (const float*)d_in[15] + j * 64;
        }
        const float* W1n = (l < 3) ? ((const float*)d_in[10] + l * 64 * 64) : (const float*)d_in[10];
        int has_next = (l < 3) ? 1 : 0;

        aggregate_kernel<<<(NN * 32 + 255) / 256, 256>>>(eps, l, b1);
        gemm_dual_kernel<<<(NN + 127) / 128, 256>>>(W2, b2, batch, l * 64, W1n, has_next, NN,
                                                    l, gg, be, 1.0f / (float)NN);
    }

    head1_kernel<<<NG, 64>>>((const float*)d_in[16], (const float*)d_in[17]);
    head_bn_kernel<<<64, 256>>>((const float*)d_in[18], (const float*)d_in[19]);
    head_final_kernel<<<NG, 64>>>((const float*)d_in[20], (const float*)d_in[21], (float*)d_out);
}

// round 14
// speedup vs baseline: 2.1582x; 1.0034x over previous
#include <cuda_runtime.h>
#include <cuda_bf16.h>
#include <math.h>

#define NN 100000
#define NE 1600000
#define NG 512
#define NSB 98   // scan blocks of 1024 -> covers 100352 >= NN

// ---------------- device scratch ----------------
__device__ __align__(256) __nv_bfloat162 g_yb[NN * 32];  // y in bf16x2: 128B/node
__device__ __align__(256) float g_t[NN * 64];
__device__ float g_stats[4 * 128];
__device__ float g_scale[64];
__device__ float g_shift[64];
__device__ float g_pooled[NG * 256];
__device__ float g_head1[NG * 64];
__device__ int   g_deg[NN];
__device__ int   g_off[NN + 1];
__device__ int   g_cursor[NN];
__device__ int   g_srcs[NE];
__device__ int   g_bsum[NSB];

// ---------------- tf32 mma (raw fp32 bits in; HW reads tf32 fields = truncation) ----------------
__device__ __forceinline__ void mma_tf32(float* d,
                                         unsigned a0, unsigned a1, unsigned a2, unsigned a3,
                                         unsigned b0, unsigned b1) {
    asm("mma.sync.aligned.m16n8k8.row.col.f32.tf32.tf32.f32 "
        "{%0,%1,%2,%3}, {%4,%5,%6,%7}, {%8,%9}, {%0,%1,%2,%3};"
        : "+f"(d[0]), "+f"(d[1]), "+f"(d[2]), "+f"(d[3])
        : "r"(a0), "r"(a1), "r"(a2), "r"(a3), "r"(b0), "r"(b1));
}

// ---------------- fused zero kernel ----------------
#define ZW (131072 + 512 + NN)
__global__ void zero_all_kernel() {
    int i = blockIdx.x * 256 + threadIdx.x;
    if (i < 131072) g_pooled[i] = 0.f;
    else if (i < 131072 + 512) g_stats[i - 131072] = 0.f;
    else if (i < ZW) g_deg[i - 131072 - 512] = 0;
}

// ---------------- CSR build ----------------
__global__ void hist_kernel(const int* __restrict__ ei) {
    int e = blockIdx.x * 256 + threadIdx.x;
    if (e < NE) atomicAdd(&g_deg[ei[NE + e]], 1);
}
__global__ void scan1_kernel() {                  // <<<NSB,1024>>>
    __shared__ int wsum[32];
    int tid = threadIdx.x;
    int i = blockIdx.x * 1024 + tid;
    int v = (i < NN) ? g_deg[i] : 0;
    int x = v;
    #pragma unroll
    for (int o = 1; o < 32; o <<= 1) {
        int t = __shfl_up_sync(0xffffffffu, x, o);
        if ((tid & 31) >= o) x += t;
    }
    if ((tid & 31) == 31) wsum[tid >> 5] = x;
    __syncthreads();
    if (tid < 32) {
        int y = wsum[tid];
        #pragma unroll
        for (int o = 1; o < 32; o <<= 1) {
            int t = __shfl_up_sync(0xffffffffu, y, o);
            if (tid >= o) y += t;
        }
        wsum[tid] = y;
    }
    __syncthreads();
    int base = (tid >= 32) ? wsum[(tid >> 5) - 1] : 0;
    int incl = x + base;
    if (i < NN) g_off[i] = incl - v;
    if (tid == 1023) g_bsum[blockIdx.x] = incl;
}
// scan3: each block redundantly scans the NSB block sums (absorbs old scan2)
__global__ void scan3_kernel() {                  // <<<NSB,1024>>>
    __shared__ int bs[128];
    int tid = threadIdx.x;
    if (tid < 128) bs[tid] = (tid < NSB) ? g_bsum[tid] : 0;
    __syncthreads();
    #pragma unroll
    for (int o = 1; o < 128; o <<= 1) {
        int t = 0;
        if (tid < 128 && tid >= o) t = bs[tid - o];
        __syncthreads();
        if (tid < 128) bs[tid] += t;
        __syncthreads();
    }
    int base = (blockIdx.x > 0) ? bs[blockIdx.x - 1] : 0;
    int i = blockIdx.x * 1024 + tid;
    if (i < NN) {
        int v = g_off[i] + base;
        g_off[i] = v;
        g_cursor[i] = v;
    }
    if (i == 0) g_off[NN] = NE;
}
__global__ void csr_scatter_kernel(const int* __restrict__ ei) {
    int e = blockIdx.x * 256 + threadIdx.x;
    if (e < NE) {
        int s = ei[e];
        int d = ei[NE + e];
        int p = atomicAdd(&g_cursor[d], 1);
        g_srcs[p] = s;
    }
}

// ---------------- gemm_pre (TF32 mma.sync, 8 warps M/N-split): y = X @ W1_0, bf16 store ----
// block = 64 nodes, 256 thr. warp w: rows (w&3)*16, cols (w>>2)*32, K=128
__global__ void __launch_bounds__(256) gemm_pre_kernel(
    const float* __restrict__ X, const float* __restrict__ W, int N)
{
    __shared__ float sX[64 * 132];    // fp32 bits [row][k], stride 132
    __shared__ float sW[128 * 72];    // W [k][n] direct, stride 72 (conflict-free B-frags)
    int tid = threadIdx.x, wid = tid >> 5, lid = tid & 31;
    int gi = lid >> 2, ti = lid & 3;
    int base = blockIdx.x * 64;

    const float4* Xv = (const float4*)X;
    #pragma unroll 4
    for (int i = tid; i < 2048; i += 256) {
        int row = i >> 5, q = i & 31;
        float4 v = make_float4(0.f, 0.f, 0.f, 0.f);
        int r = base + row;
        if (r < N) v = Xv[r * 32 + q];
        *(float4*)&sX[row * 132 + q * 4] = v;
    }
    const float4* Wv = (const float4*)W;
    #pragma unroll 4
    for (int i = tid; i < 2048; i += 256) {
        int k = i >> 4, q = i & 15;
        *(float4*)&sW[k * 72 + q * 4] = Wv[i];
    }
    __syncthreads();

    int arow = (wid & 3) * 16 + gi;
    int ng = (wid >> 2) * 32;
    float e[4][4];
    #pragma unroll
    for (int j = 0; j < 4; j++) { e[j][0] = 0.f; e[j][1] = 0.f; e[j][2] = 0.f; e[j][3] = 0.f; }
    #pragma unroll
    for (int t = 0; t < 16; t++) {
        int kb = t * 8;
        unsigned a0 = __float_as_uint(sX[arow * 132 + kb + ti]);
        unsigned a1 = __float_as_uint(sX[(arow + 8) * 132 + kb + ti]);
        unsigned a2 = __float_as_uint(sX[arow * 132 + kb + ti + 4]);
        unsigned a3 = __float_as_uint(sX[(arow + 8) * 132 + kb + ti + 4]);
        #pragma unroll
        for (int j = 0; j < 4; j++) {
            unsigned b0 = __float_as_uint(sW[(kb + ti) * 72 + ng + 8 * j + gi]);
            unsigned b1 = __float_as_uint(sW[(kb + ti + 4) * 72 + ng + 8 * j + gi]);
            mma_tf32(e[j], a0, a1, a2, a3, b0, b1);
        }
    }
    int r0 = base + arow, r1 = base + arow + 8;
    int cpb = ng >> 1;
    if (r0 < N) {
        #pragma unroll
        for (int j = 0; j < 4; j++)
            g_yb[r0 * 32 + cpb + 4 * j + ti] = __floats2bfloat162_rn(e[j][0], e[j][1]);
    }
    if (r1 < N) {
        #pragma unroll
        for (int j = 0; j < 4; j++)
            g_yb[r1 * 32 + cpb + 4 * j + ti] = __floats2bfloat162_rn(e[j][2], e[j][3]);
    }
}

// ---------------- aggregate: warp/node, t = (1+eps)y + gather(y) + b1; BN stats ----------------
__global__ void __launch_bounds__(256) aggregate_kernel(
    const float* __restrict__ eps_arr, int layer, const float* __restrict__ b1)
{
    __shared__ float ss[128];
    int tid = threadIdx.x;
    if (tid < 128) ss[tid] = 0.f;
    __syncthreads();

    int warp = (blockIdx.x * 256 + tid) >> 5;
    int lane = tid & 31;
    if (warp < NN) {
        float oe = 1.0f + __ldg(&eps_arr[layer]);
        int beg = g_off[warp], end = g_off[warp + 1];
        float2 self = __bfloat1622float2(g_yb[warp * 32 + lane]);
        float2 acc = make_float2(self.x * oe, self.y * oe);
        // software pipeline: prefetch next 32-edge index block
        int idx = (beg + lane < end) ? g_srcs[beg + lane] : 0;
        for (int bse = beg; bse < end; bse += 32) {
            int m = end - bse; if (m > 32) m = 32;
            int nb = bse + 32;
            int idx_next = (nb + lane < end) ? g_srcs[nb + lane] : 0;
            int t = 0;
            for (; t + 4 <= m; t += 4) {
                int s0 = __shfl_sync(0xffffffffu, idx, t);
                int s1 = __shfl_sync(0xffffffffu, idx, t + 1);
                int s2 = __shfl_sync(0xffffffffu, idx, t + 2);
                int s3 = __shfl_sync(0xffffffffu, idx, t + 3);
                float2 a = __bfloat1622float2(g_yb[s0 * 32 + lane]);
                float2 b = __bfloat1622float2(g_yb[s1 * 32 + lane]);
                float2 cc = __bfloat1622float2(g_yb[s2 * 32 + lane]);
                float2 d = __bfloat1622float2(g_yb[s3 * 32 + lane]);
                acc.x += (a.x + b.x) + (cc.x + d.x);
                acc.y += (a.y + b.y) + (cc.y + d.y);
            }
            for (; t < m; t++) {
                int s0 = __shfl_sync(0xffffffffu, idx, t);
                float2 a = __bfloat1622float2(g_yb[s0 * 32 + lane]);
                acc.x += a.x; acc.y += a.y;
            }
            idx = idx_next;
        }
        float2 bb = *(const float2*)&b1[2 * lane];
        acc.x += bb.x; acc.y += bb.y;
        *(float2*)&g_t[warp * 64 + 2 * lane] = acc;
        atomicAdd(&ss[2 * lane], acc.x);
        atomicAdd(&ss[2 * lane + 1], acc.y);
        atomicAdd(&ss[64 + 2 * lane], acc.x * acc.x);
        atomicAdd(&ss[64 + 2 * lane + 1], acc.y * acc.y);
    }
    __syncthreads();
    if (tid < 128) atomicAdd(&g_stats[layer * 128 + tid], ss[tid]);
}

// ---------------- gemm_dual (TF32 mma.sync): z=relu(bn(t)); H=relu(z@W2+b2);
//                  y_next = H@W1n (bf16 out); pool H ----------------
// block = 128 nodes, 8 warps; warp = 16-row m-tile x 64 cols (8 n-tiles), K=64 (8 k-steps)
__global__ void __launch_bounds__(256) gemm_dual_kernel(
    const float* __restrict__ W2, const float* __restrict__ B2,
    const int* __restrict__ batch, int pool_off,
    const float* __restrict__ W1n, int has_next, int N,
    int layer, const float* __restrict__ gg, const float* __restrict__ be, float ninv)
{
    __shared__ float sA[128 * 68];    // A (z, fp32 bits) -> reused for H (f32)
    __shared__ float sB2[64 * 72];    // W2 [k][n] direct, stride 72 (conflict-free B-frags)
    __shared__ float sB1[64 * 72];    // W1n [k][n] direct
    __shared__ float scs[64], shs[64], b2s[64];
    int tid = threadIdx.x, wid = tid >> 5, lid = tid & 31;
    int gi = lid >> 2, ti = lid & 3;

    if (tid < 64) {
        float mean = g_stats[layer * 128 + tid] * ninv;
        float var  = g_stats[layer * 128 + 64 + tid] * ninv - mean * mean;
        float s = gg[tid] * rsqrtf(var + 1e-5f);
        scs[tid] = s;
        shs[tid] = fmaf(-mean, s, be[tid]);
        b2s[tid] = B2[tid];
    }
    __syncthreads();

    // stage A = relu(bn(g_t)): [row][k], stride 68 (raw fp32 bits into tf32 MMA)
    int base = blockIdx.x * 128;
    #pragma unroll 2
    for (int i = tid; i < 2048; i += 256) {
        int row = i >> 4, u = i & 15;
        float4 v = make_float4(0.f, 0.f, 0.f, 0.f);
        int r = base + row;
        if (r < N) {
            float4 t = ((const float4*)g_t)[r * 16 + u];
            int cb = u * 4;
            v.x = fmaxf(fmaf(t.x, scs[cb + 0], shs[cb + 0]), 0.f);
            v.y = fmaxf(fmaf(t.y, scs[cb + 1], shs[cb + 1]), 0.f);
            v.z = fmaxf(fmaf(t.z, scs[cb + 2], shs[cb + 2]), 0.f);
            v.w = fmaxf(fmaf(t.w, scs[cb + 3], shs[cb + 3]), 0.f);
        }
        *(float4*)&sA[row * 68 + u * 4] = v;
    }
    // stage B2/B1 direct [k][n], float4 coalesced (raw fp32 bits)
    {
        const float4* Wv = (const float4*)W2;
        #pragma unroll 2
        for (int i = tid; i < 1024; i += 256) {
            int k = i >> 4, q = i & 15;
            *(float4*)&sB2[k * 72 + q * 4] = Wv[i];
        }
    }
    if (has_next) {
        const float4* Wv = (const float4*)W1n;
        #pragma unroll 2
        for (int i = tid; i < 1024; i += 256) {
            int k = i >> 4, q = i & 15;
            *(float4*)&sB1[k * 72 + q * 4] = Wv[i];
        }
    }
    __syncthreads();

    // MMA1: D = A @ W2, bias pre-loaded
    int arow = wid * 16 + gi;
    float d[8][4];
    #pragma unroll
    for (int j = 0; j < 8; j++) {
        float bb0 = b2s[8 * j + 2 * ti], bb1 = b2s[8 * j + 2 * ti + 1];
        d[j][0] = bb0; d[j][1] = bb1; d[j][2] = bb0; d[j][3] = bb1;
    }
    #pragma unroll
    for (int t = 0; t < 8; t++) {
        int kb = t * 8;
        unsigned a0 = __float_as_uint(sA[arow * 68 + kb + ti]);
        unsigned a1 = __float_as_uint(sA[(arow + 8) * 68 + kb + ti]);
        unsigned a2 = __float_as_uint(sA[arow * 68 + kb + ti + 4]);
        unsigned a3 = __float_as_uint(sA[(arow + 8) * 68 + kb + ti + 4]);
        #pragma unroll
        for (int j = 0; j < 8; j++) {
            unsigned b0 = __float_as_uint(sB2[(kb + ti) * 72 + 8 * j + gi]);
            unsigned b1 = __float_as_uint(sB2[(kb + ti + 4) * 72 + 8 * j + gi]);
            mma_tf32(d[j], a0, a1, a2, a3, b0, b1);
        }
    }

    // H = relu(D); overwrite own-warp rows of sA
    #pragma unroll
    for (int j = 0; j < 8; j++) {
        float h0 = fmaxf(d[j][0], 0.f), h1 = fmaxf(d[j][1], 0.f);
        float h2 = fmaxf(d[j][2], 0.f), h3 = fmaxf(d[j][3], 0.f);
        *(float2*)&sA[arow * 68 + 8 * j + 2 * ti]       = make_float2(h0, h1);
        *(float2*)&sA[(arow + 8) * 68 + 8 * j + 2 * ti] = make_float2(h2, h3);
    }
    __syncwarp();

    // MMA2: y_next = H @ W1n, write bf16
    if (has_next) {
        float e[8][4];
        #pragma unroll
        for (int j = 0; j < 8; j++) { e[j][0] = 0.f; e[j][1] = 0.f; e[j][2] = 0.f; e[j][3] = 0.f; }
        #pragma unroll
        for (int t = 0; t < 8; t++) {
            int kb = t * 8;
            unsigned a0 = __float_as_uint(sA[arow * 68 + kb + ti]);
            unsigned a1 = __float_as_uint(sA[(arow + 8) * 68 + kb + ti]);
            unsigned a2 = __float_as_uint(sA[arow * 68 + kb + ti + 4]);
            unsigned a3 = __float_as_uint(sA[(arow + 8) * 68 + kb + ti + 4]);
            #pragma unroll
            for (int j = 0; j < 8; j++) {
                unsigned b0 = __float_as_uint(sB1[(kb + ti) * 72 + 8 * j + gi]);
                unsigned b1 = __float_as_uint(sB1[(kb + ti + 4) * 72 + 8 * j + gi]);
                mma_tf32(e[j], a0, a1, a2, a3, b0, b1);
            }
        }
        int r0 = base + arow, r1 = base + arow + 8;
        if (r0 < N) {
            #pragma unroll
            for (int j = 0; j < 8; j++)
                g_yb[r0 * 32 + 4 * j + ti] = __floats2bfloat162_rn(e[j][0], e[j][1]);
        }
        if (r1 < N) {
            #pragma unroll
            for (int j = 0; j < 8; j++)
                g_yb[r1 * 32 + 4 * j + ti] = __floats2bfloat162_rn(e[j][2], e[j][3]);
        }
    }

    // pooling from sA H (f32), run-compressed (batch sorted)
    {
        int prow = wid * 16;
        int cp = lid;
        int bprev = -1; float p0 = 0.f, p1 = 0.f;
        #pragma unroll
        for (int j = 0; j < 16; j++) {
            int rr = base + prow + j;
            if (rr < N) {
                float2 hv = *(const float2*)&sA[(prow + j) * 68 + 2 * cp];
                int bg = batch[rr];
                if (bg != bprev) {
                    if (bprev >= 0)
                        atomicAdd((float2*)&g_pooled[bprev * 256 + pool_off + 2 * cp],
                                  make_float2(p0, p1));
                    bprev = bg; p0 = 0.f; p1 = 0.f;
                }
                p0 += hv.x; p1 += hv.y;
            }
        }
        if (bprev >= 0)
            atomicAdd((float2*)&g_pooled[bprev * 256 + pool_off + 2 * cp],
                      make_float2(p0, p1));
    }
}

// ---------------- head ----------------
__global__ void head1_kernel(const float* __restrict__ W, const float* __restrict__ B)
{
    int gph = blockIdx.x, c = threadIdx.x;   // <<<512,64>>>
    __shared__ float xs[256];
    #pragma unroll
    for (int i = c; i < 256; i += 64) xs[i] = g_pooled[gph * 256 + i];
    __syncthreads();
    float a = B[c];
    #pragma unroll 4
    for (int k = 0; k < 256; k++) a = fmaf(xs[k], __ldg(&W[k * 64 + c]), a);
    g_head1[gph * 64 + c] = a;
}

__global__ void head_bn_kernel(const float* __restrict__ g, const float* __restrict__ be)
{
    int c = blockIdx.x; int t = threadIdx.x;  // <<<64,256>>>
    __shared__ float red[256];
    float v0 = g_head1[t * 64 + c];
    float v1 = g_head1[(t + 256) * 64 + c];
    red[t] = v0 + v1;
    __syncthreads();
    for (int o = 128; o > 0; o >>= 1) { if (t < o) red[t] += red[t + o]; __syncthreads(); }
    float mean = red[0] * (1.0f / 512.0f);
    __syncthreads();
    float d0 = v0 - mean, d1 = v1 - mean;
    red[t] = d0 * d0 + d1 * d1;
    __syncthreads();
    for (int o = 128; o > 0; o >>= 1) { if (t < o) red[t] += red[t + o]; __syncthreads(); }
    if (t == 0) {
        float var = red[0] * (1.0f / 512.0f);
        float s = g[c] * rsqrtf(var + 1e-5f);
        g_scale[c] = s;
        g_shift[c] = fmaf(-mean, s, be[c]);
    }
}

__global__ void head_final_kernel(const float* __restrict__ W, const float* __restrict__ B,
                                  float* __restrict__ out)
{
    int gph = blockIdx.x; int c = threadIdx.x;   // <<<512,64>>>
    __shared__ float hn[64];
    __shared__ float logits[10];
    hn[c] = fmaxf(fmaf(g_head1[gph * 64 + c], g_scale[c], g_shift[c]), 0.f);
    __syncthreads();
    if (c < 10) {
        float a = B[c];
        #pragma unroll
        for (int k = 0; k < 64; k++) a = fmaf(hn[k], W[k * 10 + c], a);
        logits[c] = a;
    }
    __syncthreads();
    if (c == 0) {
        float m = logits[0];
        #pragma unroll
        for (int j = 1; j < 10; j++) m = fmaxf(m, logits[j]);
        float ssum = 0.f;
        #pragma unroll
        for (int j = 0; j < 10; j++) ssum += expf(logits[j] - m);
        float lse = m + logf(ssum);
        #pragma unroll
        for (int j = 0; j < 10; j++) out[gph * 10 + j] = logits[j] - lse;
    }
}

// ---------------- launch ----------------
extern "C" void kernel_launch(void* const* d_in, const int* in_sizes, int n_in,
                              void* d_out, int out_size)
{
    const float* x     = (const float*)d_in[0];
    const int*   ei    = (const int*)d_in[1];
    const int*   batch = (const int*)d_in[2];
    const float* eps   = (const float*)d_in[3];

    zero_all_kernel<<<(ZW + 255) / 256, 256>>>();                 // 1
    hist_kernel<<<(NE + 255) / 256, 256>>>(ei);                   // 2
    scan1_kernel<<<NSB, 1024>>>();                                // 3
    gemm_pre_kernel<<<(NN + 63) / 64, 256>>>(x, (const float*)d_in[4], NN);  // 4 (profiled)
    scan3_kernel<<<NSB, 1024>>>();                                // 5
    csr_scatter_kernel<<<(NE + 255) / 256, 256>>>(ei);            // 6

    for (int l = 0; l < 4; l++) {
        const float *b1, *gg, *be, *W2, *b2;
        if (l == 0) {
            b1 = (const float*)d_in[5];
            gg = (const float*)d_in[6]; be = (const float*)d_in[7];
            W2 = (const float*)d_in[8]; b2 = (const float*)d_in[9];
        } else {
            int j = l - 1;
            b1 = (const float*)d_in[11] + j * 64;
            gg = (const float*)d_in[12] + j * 64; be = (const float*)d_in[13] + j * 64;
            W2 = (const float*)d_in[14] + j * 64 * 64; b2 = (const float*)d_in[15] + j * 64;
        }
        const float* W1n = (l < 3) ? ((const float*)d_in[10] + l * 64 * 64) : (const float*)d_in[10];
        int has_next = (l < 3) ? 1 : 0;

        aggregate_kernel<<<(NN * 32 + 255) / 256, 256>>>(eps, l, b1);
        gemm_dual_kernel<<<(NN + 127) / 128, 256>>>(W2, b2, batch, l * 64, W1n, has_next, NN,
                                                    l, gg, be, 1.0f / (float)NN);
    }

    head1_kernel<<<NG, 64>>>((const float*)d_in[16], (const float*)d_in[17]);
    head_bn_kernel<<<64, 256>>>((const float*)d_in[18], (const float*)d_in[19]);
    head_final_kernel<<<NG, 64>>>((const float*)d_in[20], (const float*)d_in[21], (float*)d_out);
}

// round 15
// speedup vs baseline: 2.2667x; 1.0503x over previous
#include <cuda_runtime.h>
#include <cuda_bf16.h>
#include <math.h>

#define NN 100000
#define NE 1600000
#define NG 512
#define NSB 98   // scan blocks of 1024 -> covers 100352 >= NN

// ---------------- device scratch ----------------
__device__ __align__(256) __nv_bfloat162 g_yb[NN * 32];  // y in bf16x2: 128B/node
__device__ __align__(256) __nv_bfloat162 g_tb[NN * 32];  // t in bf16x2: 128B/node
__device__ float g_stats[4 * 128];
__device__ float g_scale[64];
__device__ float g_shift[64];
__device__ float g_pooled[NG * 256];
__device__ float g_head1[NG * 64];
__device__ int   g_deg[NN];          // BSS zero; scan1 self-clears after use
__device__ int   g_off[NN + 1];
__device__ int   g_cursor[NN];
__device__ int   g_srcs[NE];
__device__ int   g_bsum[NSB];

// ---------------- tf32 mma (raw fp32 bits in; HW reads tf32 fields) ----------------
__device__ __forceinline__ void mma_tf32(float* d,
                                         unsigned a0, unsigned a1, unsigned a2, unsigned a3,
                                         unsigned b0, unsigned b1) {
    asm("mma.sync.aligned.m16n8k8.row.col.f32.tf32.tf32.f32 "
        "{%0,%1,%2,%3}, {%4,%5,%6,%7}, {%8,%9}, {%0,%1,%2,%3};"
        : "+f"(d[0]), "+f"(d[1]), "+f"(d[2]), "+f"(d[3])
        : "r"(a0), "r"(a1), "r"(a2), "r"(a3), "r"(b0), "r"(b1));
}

// ---------------- hist + zero fused (zeroing independent of histogram) ----------------
__global__ void hist_zero_kernel(const int* __restrict__ ei) {
    int gid = blockIdx.x * 256 + threadIdx.x;
    if (gid < 131072) g_pooled[gid] = 0.f;
    else if (gid < 131072 + 512) g_stats[gid - 131072] = 0.f;
    if (gid < NE) atomicAdd(&g_deg[ei[NE + gid]], 1);
}

// ---------------- CSR build ----------------
__global__ void scan1_kernel() {                  // <<<NSB,1024>>>
    __shared__ int wsum[32];
    int tid = threadIdx.x;
    int i = blockIdx.x * 1024 + tid;
    int v = (i < NN) ? g_deg[i] : 0;
    if (i < NN) g_deg[i] = 0;                     // self-clear for next call
    int x = v;
    #pragma unroll
    for (int o = 1; o < 32; o <<= 1) {
        int t = __shfl_up_sync(0xffffffffu, x, o);
        if ((tid & 31) >= o) x += t;
    }
    if ((tid & 31) == 31) wsum[tid >> 5] = x;
    __syncthreads();
    if (tid < 32) {
        int y = wsum[tid];
        #pragma unroll
        for (int o = 1; o < 32; o <<= 1) {
            int t = __shfl_up_sync(0xffffffffu, y, o);
            if (tid >= o) y += t;
        }
        wsum[tid] = y;
    }
    __syncthreads();
    int base = (tid >= 32) ? wsum[(tid >> 5) - 1] : 0;
    int incl = x + base;
    if (i < NN) g_off[i] = incl - v;
    if (tid == 1023) g_bsum[blockIdx.x] = incl;
}
// scan3: each block redundantly scans the NSB block sums
__global__ void scan3_kernel() {                  // <<<NSB,1024>>>
    __shared__ int bs[128];
    int tid = threadIdx.x;
    if (tid < 128) bs[tid] = (tid < NSB) ? g_bsum[tid] : 0;
    __syncthreads();
    #pragma unroll
    for (int o = 1; o < 128; o <<= 1) {
        int t = 0;
        if (tid < 128 && tid >= o) t = bs[tid - o];
        __syncthreads();
        if (tid < 128) bs[tid] += t;
        __syncthreads();
    }
    int base = (blockIdx.x > 0) ? bs[blockIdx.x - 1] : 0;
    int i = blockIdx.x * 1024 + tid;
    if (i < NN) {
        int v = g_off[i] + base;
        g_off[i] = v;
        g_cursor[i] = v;
    }
    if (i == 0) g_off[NN] = NE;
}
__global__ void csr_scatter_kernel(const int* __restrict__ ei) {
    int e = blockIdx.x * 256 + threadIdx.x;
    if (e < NE) {
        int s = ei[e];
        int d = ei[NE + e];
        int p = atomicAdd(&g_cursor[d], 1);
        g_srcs[p] = s;
    }
}

// ---------------- gemm_pre (TF32 mma.sync, 8 warps M/N-split): y = X @ W1_0, bf16 store ----
// block = 64 nodes, 256 thr. warp w: rows (w&3)*16, cols (w>>2)*32, K=128
__global__ void __launch_bounds__(256) gemm_pre_kernel(
    const float* __restrict__ X, const float* __restrict__ W, int N)
{
    __shared__ float sX[64 * 132];    // fp32 bits [row][k], stride 132
    __shared__ float sW[128 * 72];    // W [k][n] direct, stride 72 (conflict-free B-frags)
    int tid = threadIdx.x, wid = tid >> 5, lid = tid & 31;
    int gi = lid >> 2, ti = lid & 3;
    int base = blockIdx.x * 64;

    const float4* Xv = (const float4*)X;
    #pragma unroll 4
    for (int i = tid; i < 2048; i += 256) {
        int row = i >> 5, q = i & 31;
        float4 v = make_float4(0.f, 0.f, 0.f, 0.f);
        int r = base + row;
        if (r < N) v = Xv[r * 32 + q];
        *(float4*)&sX[row * 132 + q * 4] = v;
    }
    const float4* Wv = (const float4*)W;
    #pragma unroll 4
    for (int i = tid; i < 2048; i += 256) {
        int k = i >> 4, q = i & 15;
        *(float4*)&sW[k * 72 + q * 4] = Wv[i];
    }
    __syncthreads();

    int arow = (wid & 3) * 16 + gi;
    int ng = (wid >> 2) * 32;
    float e[4][4];
    #pragma unroll
    for (int j = 0; j < 4; j++) { e[j][0] = 0.f; e[j][1] = 0.f; e[j][2] = 0.f; e[j][3] = 0.f; }
    #pragma unroll
    for (int t = 0; t < 16; t++) {
        int kb = t * 8;
        unsigned a0 = __float_as_uint(sX[arow * 132 + kb + ti]);
        unsigned a1 = __float_as_uint(sX[(arow + 8) * 132 + kb + ti]);
        unsigned a2 = __float_as_uint(sX[arow * 132 + kb + ti + 4]);
        unsigned a3 = __float_as_uint(sX[(arow + 8) * 132 + kb + ti + 4]);
        #pragma unroll
        for (int j = 0; j < 4; j++) {
            unsigned b0 = __float_as_uint(sW[(kb + ti) * 72 + ng + 8 * j + gi]);
            unsigned b1 = __float_as_uint(sW[(kb + ti + 4) * 72 + ng + 8 * j + gi]);
            mma_tf32(e[j], a0, a1, a2, a3, b0, b1);
        }
    }
    int r0 = base + arow, r1 = base + arow + 8;
    int cpb = ng >> 1;
    if (r0 < N) {
        #pragma unroll
        for (int j = 0; j < 4; j++)
            g_yb[r0 * 32 + cpb + 4 * j + ti] = __floats2bfloat162_rn(e[j][0], e[j][1]);
    }
    if (r1 < N) {
        #pragma unroll
        for (int j = 0; j < 4; j++)
            g_yb[r1 * 32 + cpb + 4 * j + ti] = __floats2bfloat162_rn(e[j][2], e[j][3]);
    }
}

// ---------------- aggregate: warp/node, t = (1+eps)y + gather(y) + b1; bf16 out; BN stats ----
__global__ void __launch_bounds__(256) aggregate_kernel(
    const float* __restrict__ eps_arr, int layer, const float* __restrict__ b1)
{
    __shared__ float ss[128];
    int tid = threadIdx.x;
    if (tid < 128) ss[tid] = 0.f;
    __syncthreads();

    int warp = (blockIdx.x * 256 + tid) >> 5;
    int lane = tid & 31;
    if (warp < NN) {
        float oe = 1.0f + __ldg(&eps_arr[layer]);
        int beg = g_off[warp], end = g_off[warp + 1];
        float2 self = __bfloat1622float2(g_yb[warp * 32 + lane]);
        float2 acc = make_float2(self.x * oe, self.y * oe);
        // software pipeline: prefetch next 32-edge index block
        int idx = (beg + lane < end) ? g_srcs[beg + lane] : 0;
        for (int bse = beg; bse < end; bse += 32) {
            int m = end - bse; if (m > 32) m = 32;
            int nb = bse + 32;
            int idx_next = (nb + lane < end) ? g_srcs[nb + lane] : 0;
            int t = 0;
            for (; t + 4 <= m; t += 4) {
                int s0 = __shfl_sync(0xffffffffu, idx, t);
                int s1 = __shfl_sync(0xffffffffu, idx, t + 1);
                int s2 = __shfl_sync(0xffffffffu, idx, t + 2);
                int s3 = __shfl_sync(0xffffffffu, idx, t + 3);
                float2 a = __bfloat1622float2(g_yb[s0 * 32 + lane]);
                float2 b = __bfloat1622float2(g_yb[s1 * 32 + lane]);
                float2 cc = __bfloat1622float2(g_yb[s2 * 32 + lane]);
                float2 d = __bfloat1622float2(g_yb[s3 * 32 + lane]);
                acc.x += (a.x + b.x) + (cc.x + d.x);
                acc.y += (a.y + b.y) + (cc.y + d.y);
            }
            for (; t < m; t++) {
                int s0 = __shfl_sync(0xffffffffu, idx, t);
                float2 a = __bfloat1622float2(g_yb[s0 * 32 + lane]);
                acc.x += a.x; acc.y += a.y;
            }
            idx = idx_next;
        }
        float2 bb = *(const float2*)&b1[2 * lane];
        acc.x += bb.x; acc.y += bb.y;
        g_tb[warp * 32 + lane] = __floats2bfloat162_rn(acc.x, acc.y);
        atomicAdd(&ss[2 * lane], acc.x);
        atomicAdd(&ss[2 * lane + 1], acc.y);
        atomicAdd(&ss[64 + 2 * lane], acc.x * acc.x);
        atomicAdd(&ss[64 + 2 * lane + 1], acc.y * acc.y);
    }
    __syncthreads();
    if (tid < 128) atomicAdd(&g_stats[layer * 128 + tid], ss[tid]);
}

// ---------------- gemm_dual (TF32 mma.sync): z=relu(bn(t)); H=relu(z@W2+b2);
//                  y_next = H@W1n (bf16 out); pool H ----------------
// block = 128 nodes, 8 warps; warp = 16-row m-tile x 64 cols (8 n-tiles), K=64 (8 k-steps)
__global__ void __launch_bounds__(256) gemm_dual_kernel(
    const float* __restrict__ W2, const float* __restrict__ B2,
    const int* __restrict__ batch, int pool_off,
    const float* __restrict__ W1n, int has_next, int N,
    int layer, const float* __restrict__ gg, const float* __restrict__ be, float ninv)
{
    __shared__ float sA[128 * 68];    // A (z, fp32 bits) -> reused for H (f32)
    __shared__ float sB2[64 * 72];    // W2 [k][n] direct, stride 72 (conflict-free B-frags)
    __shared__ float sB1[64 * 72];    // W1n [k][n] direct
    __shared__ float scs[64], shs[64], b2s[64];
    int tid = threadIdx.x, wid = tid >> 5, lid = tid & 31;
    int gi = lid >> 2, ti = lid & 3;

    if (tid < 64) {
        float mean = g_stats[layer * 128 + tid] * ninv;
        float var  = g_stats[layer * 128 + 64 + tid] * ninv - mean * mean;
        float s = gg[tid] * rsqrtf(var + 1e-5f);
        scs[tid] = s;
        shs[tid] = fmaf(-mean, s, be[tid]);
        b2s[tid] = B2[tid];
    }
    __syncthreads();

    // stage A = relu(bn(g_tb)): [row][k], stride 68 (bf16 source -> fp32 smem)
    int base = blockIdx.x * 128;
    const uint2* Tb = (const uint2*)g_tb;    // 8B = 4 channels (2x bf16x2)
    #pragma unroll 2
    for (int i = tid; i < 2048; i += 256) {
        int row = i >> 4, u = i & 15;
        float4 v = make_float4(0.f, 0.f, 0.f, 0.f);
        int r = base + row;
        if (r < N) {
            uint2 tp = Tb[r * 16 + u];
            float2 t0 = __bfloat1622float2(*(__nv_bfloat162*)&tp.x);
            float2 t1 = __bfloat1622float2(*(__nv_bfloat162*)&tp.y);
            int cb = u * 4;
            v.x = fmaxf(fmaf(t0.x, scs[cb + 0], shs[cb + 0]), 0.f);
            v.y = fmaxf(fmaf(t0.y, scs[cb + 1], shs[cb + 1]), 0.f);
            v.z = fmaxf(fmaf(t1.x, scs[cb + 2], shs[cb + 2]), 0.f);
            v.w = fmaxf(fmaf(t1.y, scs[cb + 3], shs[cb + 3]), 0.f);
        }
        *(float4*)&sA[row * 68 + u * 4] = v;
    }
    // stage B2/B1 direct [k][n], float4 coalesced (raw fp32 bits)
    {
        const float4* Wv = (const float4*)W2;
        #pragma unroll 2
        for (int i = tid; i < 1024; i += 256) {
            int k = i >> 4, q = i & 15;
            *(float4*)&sB2[k * 72 + q * 4] = Wv[i];
        }
    }
    if (has_next) {
        const float4* Wv = (const float4*)W1n;
        #pragma unroll 2
        for (int i = tid; i < 1024; i += 256) {
            int k = i >> 4, q = i & 15;
            *(float4*)&sB1[k * 72 + q * 4] = Wv[i];
        }
    }
    __syncthreads();

    // MMA1: D = A @ W2, bias pre-loaded
    int arow = wid * 16 + gi;
    float d[8][4];
    #pragma unroll
    for (int j = 0; j < 8; j++) {
        float bb0 = b2s[8 * j + 2 * ti], bb1 = b2s[8 * j + 2 * ti + 1];
        d[j][0] = bb0; d[j][1] = bb1; d[j][2] = bb0; d[j][3] = bb1;
    }
    #pragma unroll
    for (int t = 0; t < 8; t++) {
        int kb = t * 8;
        unsigned a0 = __float_as_uint(sA[arow * 68 + kb + ti]);
        unsigned a1 = __float_as_uint(sA[(arow + 8) * 68 + kb + ti]);
        unsigned a2 = __float_as_uint(sA[arow * 68 + kb + ti + 4]);
        unsigned a3 = __float_as_uint(sA[(arow + 8) * 68 + kb + ti + 4]);
        #pragma unroll
        for (int j = 0; j < 8; j++) {
            unsigned b0 = __float_as_uint(sB2[(kb + ti) * 72 + 8 * j + gi]);
            unsigned b1 = __float_as_uint(sB2[(kb + ti + 4) * 72 + 8 * j + gi]);
            mma_tf32(d[j], a0, a1, a2, a3, b0, b1);
        }
    }

    // H = relu(D); overwrite own-warp rows of sA
    #pragma unroll
    for (int j = 0; j < 8; j++) {
        float h0 = fmaxf(d[j][0], 0.f), h1 = fmaxf(d[j][1], 0.f);
        float h2 = fmaxf(d[j][2], 0.f), h3 = fmaxf(d[j][3], 0.f);
        *(float2*)&sA[arow * 68 + 8 * j + 2 * ti]       = make_float2(h0, h1);
        *(float2*)&sA[(arow + 8) * 68 + 8 * j + 2 * ti] = make_float2(h2, h3);
    }
    __syncwarp();

    // MMA2: y_next = H @ W1n, write bf16
    if (has_next) {
        float e[8][4];
        #pragma unroll
        for (int j = 0; j < 8; j++) { e[j][0] = 0.f; e[j][1] = 0.f; e[j][2] = 0.f; e[j][3] = 0.f; }
        #pragma unroll
        for (int t = 0; t < 8; t++) {
            int kb = t * 8;
            unsigned a0 = __float_as_uint(sA[arow * 68 + kb + ti]);
            unsigned a1 = __float_as_uint(sA[(arow + 8) * 68 + kb + ti]);
            unsigned a2 = __float_as_uint(sA[arow * 68 + kb + ti + 4]);
            unsigned a3 = __float_as_uint(sA[(arow + 8) * 68 + kb + ti + 4]);
            #pragma unroll
            for (int j = 0; j < 8; j++) {
                unsigned b0 = __float_as_uint(sB1[(kb + ti) * 72 + 8 * j + gi]);
                unsigned b1 = __float_as_uint(sB1[(kb + ti + 4) * 72 + 8 * j + gi]);
                mma_tf32(e[j], a0, a1, a2, a3, b0, b1);
            }
        }
        int r0 = base + arow, r1 = base + arow + 8;
        if (r0 < N) {
            #pragma unroll
            for (int j = 0; j < 8; j++)
                g_yb[r0 * 32 + 4 * j + ti] = __floats2bfloat162_rn(e[j][0], e[j][1]);
        }
        if (r1 < N) {
            #pragma unroll
            for (int j = 0; j < 8; j++)
                g_yb[r1 * 32 + 4 * j + ti] = __floats2bfloat162_rn(e[j][2], e[j][3]);
        }
    }

    // pooling from sA H (f32), run-compressed (batch sorted)
    {
        int prow = wid * 16;
        int cp = lid;
        int bprev = -1; float p0 = 0.f, p1 = 0.f;
        #pragma unroll
        for (int j = 0; j < 16; j++) {
            int rr = base + prow + j;
            if (rr < N) {
                float2 hv = *(const float2*)&sA[(prow + j) * 68 + 2 * cp];
                int bg = batch[rr];
                if (bg != bprev) {
                    if (bprev >= 0)
                        atomicAdd((float2*)&g_pooled[bprev * 256 + pool_off + 2 * cp],
                                  make_float2(p0, p1));
                    bprev = bg; p0 = 0.f; p1 = 0.f;
                }
                p0 += hv.x; p1 += hv.y;
            }
        }
        if (bprev >= 0)
            atomicAdd((float2*)&g_pooled[bprev * 256 + pool_off + 2 * cp],
                      make_float2(p0, p1));
    }
}

// ---------------- head ----------------
__global__ void head1_kernel(const float* __restrict__ W, const float* __restrict__ B)
{
    int gph = blockIdx.x, c = threadIdx.x;   // <<<512,64>>>
    __shared__ float xs[256];
    #pragma unroll
    for (int i = c; i < 256; i += 64) xs[i] = g_pooled[gph * 256 + i];
    __syncthreads();
    float a = B[c];
    #pragma unroll 4
    for (int k = 0; k < 256; k++) a = fmaf(xs[k], __ldg(&W[k * 64 + c]), a);
    g_head1[gph * 64 + c] = a;
}

__global__ void head_bn_kernel(const float* __restrict__ g, const float* __restrict__ be)
{
    int c = blockIdx.x; int t = threadIdx.x;  // <<<64,256>>>
    __shared__ float red[256];
    float v0 = g_head1[t * 64 + c];
    float v1 = g_head1[(t + 256) * 64 + c];
    red[t] = v0 + v1;
    __syncthreads();
    for (int o = 128; o > 0; o >>= 1) { if (t < o) red[t] += red[t + o]; __syncthreads(); }
    float mean = red[0] * (1.0f / 512.0f);
    __syncthreads();
    float d0 = v0 - mean, d1 = v1 - mean;
    red[t] = d0 * d0 + d1 * d1;
    __syncthreads();
    for (int o = 128; o > 0; o >>= 1) { if (t < o) red[t] += red[t + o]; __syncthreads(); }
    if (t == 0) {
        float var = red[0] * (1.0f / 512.0f);
        float s = g[c] * rsqrtf(var + 1e-5f);
        g_scale[c] = s;
        g_shift[c] = fmaf(-mean, s, be[c]);
    }
}

__global__ void head_final_kernel(const float* __restrict__ W, const float* __restrict__ B,
                                  float* __restrict__ out)
{
    int gph = blockIdx.x; int c = threadIdx.x;   // <<<512,64>>>
    __shared__ float hn[64];
    __shared__ float logits[10];
    hn[c] = fmaxf(fmaf(g_head1[gph * 64 + c], g_scale[c], g_shift[c]), 0.f);
    __syncthreads();
    if (c < 10) {
        float a = B[c];
        #pragma unroll
        for (int k = 0; k < 64; k++) a = fmaf(hn[k], W[k * 10 + c], a);
        logits[c] = a;
    }
    __syncthreads();
    if (c == 0) {
        float m = logits[0];
        #pragma unroll
        for (int j = 1; j < 10; j++) m = fmaxf(m, logits[j]);
        float ssum = 0.f;
        #pragma unroll
        for (int j = 0; j < 10; j++) ssum += expf(logits[j] - m);
        float lse = m + logf(ssum);
        #pragma unroll
        for (int j = 0; j < 10; j++) out[gph * 10 + j] = logits[j] - lse;
    }
}

// ---------------- launch ----------------
extern "C" void kernel_launch(void* const* d_in, const int* in_sizes, int n_in,
                              void* d_out, int out_size)
{
    const float* x     = (const float*)d_in[0];
    const int*   ei    = (const int*)d_in[1];
    const int*   batch = (const int*)d_in[2];
    const float* eps   = (const float*)d_in[3];

    hist_zero_kernel<<<(NE + 255) / 256, 256>>>(ei);              // 1 (zero pooled/stats + hist)
    scan1_kernel<<<NSB, 1024>>>();                                // 2 (self-clears g_deg)
    scan3_kernel<<<NSB, 1024>>>();                                // 3
    gemm_pre_kernel<<<(NN + 63) / 64, 256>>>(x, (const float*)d_in[4], NN);  // 4 (profiled)
    csr_scatter_kernel<<<(NE + 255) / 256, 256>>>(ei);            // 5

    for (int l = 0; l < 4; l++) {
        const float *b1, *gg, *be, *W2, *b2;
        if (l == 0) {
            b1 = (const float*)d_in[5];
            gg = (const float*)d_in[6]; be = (const float*)d_in[7];
            W2 = (const float*)d_in[8]; b2 = (const float*)d_in[9];
        } else {
            int j = l - 1;
            b1 = (const float*)d_in[11] + j * 64;
            gg = (const float*)d_in[12] + j * 64; be = (const float*)d_in[13] + j * 64;
            W2 = (const float*)d_in[14] + j * 64 * 64; b2 = (const float*)d_in[15] + j * 64;
        }
        const float* W1n = (l < 3) ? ((const float*)d_in[10] + l * 64 * 64) : (const float*)d_in[10];
        int has_next = (l < 3) ? 1 : 0;

        aggregate_kernel<<<(NN * 32 + 255) / 256, 256>>>(eps, l, b1);
        gemm_dual_kernel<<<(NN + 127) / 128, 256>>>(W2, b2, batch, l * 64, W1n, has_next, NN,
                                                    l, gg, be, 1.0f / (float)NN);
    }

    head1_kernel<<<NG, 64>>>((const float*)d_in[16], (const float*)d_in[17]);
    head_bn_kernel<<<64, 256>>>((const float*)d_in[18], (const float*)d_in[19]);
    head_final_kernel<<<NG, 64>>>((const float*)d_in[20], (const float*)d_in[21], (float*)d_out);
}